// round 1
// baseline (speedup 1.0000x reference)
#include <cuda_runtime.h>
#include <mma.h>
#include <math.h>

using namespace nvcuda;

#define NE 7
#define TOPK 2
#define CAPACITY 3072
#define DM 1024
#define DFF 4096
#define NT 8192
#define TK (NT * TOPK)

// ---------------- scratch (device globals; no allocations allowed) ----------
__device__ int   g_te[TK];                       // expert id per (t,k)
__device__ float g_tw[TK];                       // combine weight per (t,k)
__device__ int   g_src[NE * CAPACITY];           // token index per expert slot
__device__ int   g_cnt[NE];                      // tokens kept per expert
__device__ int   g_cidx[TK];                     // flat y row index per (t,k)
__device__ float g_cw[TK];                       // weight (0 if dropped)
__device__ float g_h[(size_t)NE * CAPACITY * DFF];  // gelu(buf @ W1)
__device__ float g_y[(size_t)NE * CAPACITY * DM];   // h @ W2

// ---------------- router: softmax + top2 + normalized weights ---------------
// one warp per token; Wg (1024x7 = 28KB) stays in L1.
__global__ void __launch_bounds__(256) router_kernel(const float* __restrict__ x,
                                                     const float* __restrict__ Wg) {
    int wid  = threadIdx.x >> 5;
    int lane = threadIdx.x & 31;
    int t = blockIdx.x * 8 + wid;
    if (t >= NT) return;

    float acc[NE];
#pragma unroll
    for (int e = 0; e < NE; e++) acc[e] = 0.f;

    const float4* xr = reinterpret_cast<const float4*>(x + (size_t)t * DM);
#pragma unroll 4
    for (int i = lane; i < DM / 4; i += 32) {
        float4 v = xr[i];
        int d = i * 4;
#pragma unroll
        for (int e = 0; e < NE; e++) {
            acc[e] += v.x * Wg[(d + 0) * NE + e];
            acc[e] += v.y * Wg[(d + 1) * NE + e];
            acc[e] += v.z * Wg[(d + 2) * NE + e];
            acc[e] += v.w * Wg[(d + 3) * NE + e];
        }
    }
#pragma unroll
    for (int e = 0; e < NE; e++)
#pragma unroll
        for (int off = 16; off > 0; off >>= 1)
            acc[e] += __shfl_xor_sync(0xffffffffu, acc[e], off);

    if (lane == 0) {
        float l0 = -1e30f; int e0 = 0;
#pragma unroll
        for (int e = 0; e < NE; e++) if (acc[e] > l0) { l0 = acc[e]; e0 = e; }
        float l1 = -1e30f; int e1 = 0;
#pragma unroll
        for (int e = 0; e < NE; e++) if (e != e0 && acc[e] > l1) { l1 = acc[e]; e1 = e; }
        float w0 = 1.f / (1.f + __expf(l1 - l0));   // exp cancels softmax denom
        g_te[2 * t]     = e0;  g_te[2 * t + 1] = e1;
        g_tw[2 * t]     = w0;  g_tw[2 * t + 1] = 1.f - w0;
    }
}

// ---------------- ordered capacity scan (single block, ballot-based) --------
__global__ void __launch_bounds__(256) scan_kernel() {
    __shared__ int s_run[NE];
    __shared__ int s_wtot[8][NE];
    int tid  = threadIdx.x;
    int wid  = tid >> 5;
    int lane = tid & 31;
    if (tid < NE) s_run[tid] = 0;
    __syncthreads();

    for (int base = 0; base < TK; base += 256) {
        int i = base + tid;
        int e = g_te[i];
        int rank = 0;
#pragma unroll
        for (int ee = 0; ee < NE; ee++) {
            unsigned m = __ballot_sync(0xffffffffu, e == ee);
            if (e == ee) rank = __popc(m & ((1u << lane) - 1u));
            if (lane == 0) s_wtot[wid][ee] = __popc(m);
        }
        __syncthreads();
        int off = s_run[e];
        for (int w = 0; w < wid; w++) off += s_wtot[w][e];
        int pos = off + rank;
        if (pos < CAPACITY) {
            g_src[e * CAPACITY + pos] = i >> 1;
            g_cidx[i] = e * CAPACITY + pos;
            g_cw[i]   = g_tw[i];
        } else {
            g_cidx[i] = 0;      // valid row, weight 0
            g_cw[i]   = 0.f;
        }
        __syncthreads();
        if (tid < NE) {
            int tot = 0;
#pragma unroll
            for (int w = 0; w < 8; w++) tot += s_wtot[w][tid];
            s_run[tid] += tot;
        }
        __syncthreads();
    }
    if (tid < NE) g_cnt[tid] = min(s_run[tid], CAPACITY);
    __syncthreads();
    // pad: unfilled slots point at token 0 (their outputs are never combined)
    for (int idx = tid; idx < NE * CAPACITY; idx += 256) {
        int e = idx / CAPACITY, c = idx % CAPACITY;
        if (c >= min(s_run[e], CAPACITY)) g_src[idx] = 0;
    }
}

// ---------------- grouped GEMM (tf32 wmma, 128x128x16, double-buffered) -----
__device__ __forceinline__ float gelu_tanh(float v) {
    float c = 0.7978845608028654f * (v + 0.044715f * v * v * v);
    return 0.5f * v * (1.f + tanhf(c));
}

#define BM 128
#define BN 128
#define BK 16

template <bool GEMM1>
__global__ void __launch_bounds__(256) moe_gemm(const float* __restrict__ Xin,
                                                const float* __restrict__ W) {
    constexpr int Kd = GEMM1 ? DM : DFF;
    constexpr int Nd = GEMM1 ? DFF : DM;

    int e  = blockIdx.z;
    int m0 = blockIdx.y * BM;
    int n0 = blockIdx.x * BN;
    if (m0 >= g_cnt[e]) return;          // skip fully-empty row tiles

    const float* B = W + (size_t)e * Kd * Nd;

    __shared__ __align__(16) float As[2][BM][BK + 4];
    __shared__ __align__(16) float Bs[2][BK][BN + 4];
    __shared__ const float* s_arow[BM];

    int tid = threadIdx.x;
    for (int r = tid; r < BM; r += 256) {
        if (GEMM1) {
            int tok = g_src[e * CAPACITY + m0 + r];
            s_arow[r] = Xin + (size_t)tok * Kd;
        } else {
            s_arow[r] = g_h + (size_t)(e * CAPACITY + m0 + r) * Kd;
        }
    }
    __syncthreads();

    auto loadA = [&](int buf, int k0) {
#pragma unroll
        for (int it = 0; it < 2; it++) {
            int idx = tid * 2 + it;
            int r = idx >> 2, c4 = idx & 3;
            float4 v = *reinterpret_cast<const float4*>(s_arow[r] + k0 + c4 * 4);
            *reinterpret_cast<float4*>(&As[buf][r][c4 * 4]) = v;
        }
    };
    auto loadB = [&](int buf, int k0) {
#pragma unroll
        for (int it = 0; it < 2; it++) {
            int idx = tid * 2 + it;
            int r = idx >> 5, c4 = idx & 31;
            float4 v = *reinterpret_cast<const float4*>(B + (size_t)(k0 + r) * Nd + n0 + c4 * 4);
            *reinterpret_cast<float4*>(&Bs[buf][r][c4 * 4]) = v;
        }
    };

    typedef wmma::fragment<wmma::matrix_a, 16, 16, 8, wmma::precision::tf32, wmma::row_major> FragA;
    typedef wmma::fragment<wmma::matrix_b, 16, 16, 8, wmma::precision::tf32, wmma::row_major> FragB;
    typedef wmma::fragment<wmma::accumulator, 16, 16, 8, float> FragC;

    FragC acc[4][2];
#pragma unroll
    for (int i = 0; i < 4; i++)
#pragma unroll
        for (int j = 0; j < 2; j++) wmma::fill_fragment(acc[i][j], 0.f);

    int w  = tid >> 5;
    int wm = w >> 2;   // 0..1  -> 64-row half
    int wn = w & 3;    // 0..3  -> 32-col quarter

    constexpr int nk = Kd / BK;
    loadA(0, 0);
    loadB(0, 0);
    __syncthreads();

    for (int ks = 0; ks < nk; ks++) {
        int cur = ks & 1;
        if (ks + 1 < nk) { loadA(cur ^ 1, (ks + 1) * BK); loadB(cur ^ 1, (ks + 1) * BK); }
#pragma unroll
        for (int kk = 0; kk < 2; kk++) {
            FragA af[4];
            FragB bf[2];
#pragma unroll
            for (int i = 0; i < 4; i++) {
                wmma::load_matrix_sync(af[i], &As[cur][wm * 64 + i * 16][kk * 8], BK + 4);
#pragma unroll
                for (int t = 0; t < af[i].num_elements; t++)
                    af[i].x[t] = wmma::__float_to_tf32(af[i].x[t]);
            }
#pragma unroll
            for (int j = 0; j < 2; j++) {
                wmma::load_matrix_sync(bf[j], &Bs[cur][kk * 8][wn * 32 + j * 16], BN + 4);
#pragma unroll
                for (int t = 0; t < bf[j].num_elements; t++)
                    bf[j].x[t] = wmma::__float_to_tf32(bf[j].x[t]);
            }
#pragma unroll
            for (int i = 0; i < 4; i++)
#pragma unroll
                for (int j = 0; j < 2; j++)
                    wmma::mma_sync(acc[i][j], af[i], bf[j], acc[i][j]);
        }
        __syncthreads();
    }

    float* Cb = (GEMM1 ? g_h : g_y) + (size_t)(e * CAPACITY + m0) * Nd + n0;
#pragma unroll
    for (int i = 0; i < 4; i++)
#pragma unroll
        for (int j = 0; j < 2; j++) {
            if (GEMM1) {
#pragma unroll
                for (int t = 0; t < acc[i][j].num_elements; t++)
                    acc[i][j].x[t] = gelu_tanh(acc[i][j].x[t]);
            }
            wmma::store_matrix_sync(Cb + (size_t)(wm * 64 + i * 16) * Nd + wn * 32 + j * 16,
                                    acc[i][j], Nd, wmma::mem_row_major);
        }
}

// ---------------- combine ---------------------------------------------------
__global__ void __launch_bounds__(256) combine_kernel(float* __restrict__ out) {
    int t   = blockIdx.x;
    int tid = threadIdx.x;
    int i0 = g_cidx[2 * t],     i1 = g_cidx[2 * t + 1];
    float w0 = g_cw[2 * t],     w1 = g_cw[2 * t + 1];
    const float4* y0 = reinterpret_cast<const float4*>(g_y + (size_t)i0 * DM);
    const float4* y1 = reinterpret_cast<const float4*>(g_y + (size_t)i1 * DM);
    float4 a = y0[tid], b = y1[tid];
    float4 r;
    r.x = w0 * a.x + w1 * b.x;
    r.y = w0 * a.y + w1 * b.y;
    r.z = w0 * a.z + w1 * b.z;
    r.w = w0 * a.w + w1 * b.w;
    reinterpret_cast<float4*>(out + (size_t)t * DM)[tid] = r;
}

// ---------------- launch -----------------------------------------------------
extern "C" void kernel_launch(void* const* d_in, const int* in_sizes, int n_in,
                              void* d_out, int out_size) {
    const float* x  = (const float*)d_in[0];   // [T, D]
    const float* Wg = (const float*)d_in[1];   // [D, E]
    const float* W1 = (const float*)d_in[2];   // [E, D, H]
    const float* W2 = (const float*)d_in[3];   // [E, H, D]
    float* out = (float*)d_out;                // [T, D]

    router_kernel<<<NT / 8, 256>>>(x, Wg);
    scan_kernel<<<1, 256>>>();
    moe_gemm<true ><<<dim3(DFF / BN, CAPACITY / BM, NE), 256>>>(x, W1);
    moe_gemm<false><<<dim3(DM  / BN, CAPACITY / BM, NE), 256>>>(x, W2);
    combine_kernel<<<NT, 256>>>(out);
}

// round 6
// speedup vs baseline: 5.0472x; 5.0472x over previous
#include <cuda_runtime.h>
#include <mma.h>
#include <math.h>
#include <stdint.h>

#define NE 7
#define TOPK 2
#define CAPACITY 3072
#define DM 1024
#define DFF 4096
#define NT 8192
#define TK (NT*TOPK)

#if defined(__CUDA_ARCH__) && defined(__CUDA_ARCH_FEAT_SM103_ALL)
#define HAS_TC 1
#else
#define HAS_TC 0
#endif

// ---------------- scratch (device globals; no allocations allowed) ----------
__device__ int   g_te[TK];
__device__ float g_tw[TK];
__device__ int   g_src[NE*CAPACITY];
__device__ int   g_cnt[NE];
__device__ int   g_cidx[TK];
__device__ float g_cw[TK];
__device__ float g_xr[(size_t)NT*DM];                    // tf32-rounded x
__device__ float g_w1t[(size_t)NE*(size_t)DFF*DM];       // W1^T  [e][n][k] tf32
__device__ float g_w2t[(size_t)NE*(size_t)DM*DFF];       // W2^T  [e][n][k] tf32
__device__ float g_h[(size_t)NE*CAPACITY*DFF];           // gelu(buf@W1), tf32-rounded
__device__ float g_y[(size_t)NE*CAPACITY*DM];            // h@W2

// ---------------- common helpers ---------------------------------------------
__device__ __forceinline__ float to_tf32(float f) {
    float r; asm("cvt.rna.tf32.f32 %0, %1;" : "=f"(r) : "f"(f)); return r;
}
__device__ __forceinline__ float gelu_tanh(float v) {
    float c = 0.7978845608028654f * (v + 0.044715f * v * v * v);
    return 0.5f * v * (1.f + tanhf(c));
}
__device__ __forceinline__ uint32_t smem_u32(const void* p) {
    uint32_t a;
    asm("{ .reg .u64 t; cvta.to.shared.u64 t, %1; cvt.u32.u64 %0, t; }" : "=r"(a) : "l"(p));
    return a;
}

#if HAS_TC
// ---------------- tcgen05-only PTX helpers -----------------------------------
__device__ __forceinline__ uint32_t elect_one() {
    uint32_t p;
    asm volatile("{\n\t.reg .pred p;\n\telect.sync _|p, 0xFFFFFFFF;\n\tselp.b32 %0, 1, 0, p;\n\t}" : "=r"(p));
    return p;
}
__device__ __forceinline__ uint32_t swz(uint32_t b) { return b ^ ((b >> 3) & 0x70); }

__device__ __forceinline__ void cp16(uint32_t dst, const void* src) {
    asm volatile("cp.async.cg.shared.global [%0], [%1], 16;" :: "r"(dst), "l"(src) : "memory");
}
#define CP_COMMIT() asm volatile("cp.async.commit_group;" ::: "memory")
#define CP_WAIT3()  asm volatile("cp.async.wait_group 3;" ::: "memory")

__device__ __forceinline__ void mbar_init(uint32_t a) {
    asm volatile("mbarrier.init.shared.b64 [%0], %1;" :: "r"(a), "r"(1u) : "memory");
}
__device__ __forceinline__ void mbar_wait(uint32_t a, uint32_t parity) {
    asm volatile(
        "{\n\t.reg .pred P;\n\t"
        "WAITLOOP_%=:\n\t"
        "mbarrier.try_wait.parity.acquire.cta.shared::cta.b64 P, [%0], %1, 0x989680;\n\t"
        "@P bra.uni WDONE_%=;\n\t"
        "bra.uni WAITLOOP_%=;\n\t"
        "WDONE_%=:\n\t}"
        :: "r"(a), "r"(parity) : "memory");
}

#define TC_ALLOC(smaddr, n)  asm volatile("tcgen05.alloc.cta_group::1.sync.aligned.shared::cta.b32 [%0], %1;" :: "r"(smaddr), "r"((uint32_t)(n)) : "memory")
#define TC_DEALLOC(tm, n)    asm volatile("tcgen05.dealloc.cta_group::1.sync.aligned.b32 %0, %1;" :: "r"(tm), "r"((uint32_t)(n)))
#define TC_RELINQ()          asm volatile("tcgen05.relinquish_alloc_permit.cta_group::1.sync.aligned;")
#define TC_COMMIT(mb)        asm volatile("tcgen05.commit.cta_group::1.mbarrier::arrive::one.shared::cluster.b64 [%0];" :: "r"(mb) : "memory")
#define TC_WAIT_LD()         asm volatile("tcgen05.wait::ld.sync.aligned;" ::: "memory")
#define TC_FENCE_BEFORE()    asm volatile("tcgen05.fence::before_thread_sync;" ::: "memory")
#define TC_FENCE_AFTER()     asm volatile("tcgen05.fence::after_thread_sync;" ::: "memory")
#define FENCE_ASYNC_SHARED() asm volatile("fence.proxy.async.shared::cta;" ::: "memory")

__device__ __forceinline__ void mma_tf32_ss(uint32_t d, uint64_t ad, uint64_t bd,
                                            uint32_t idesc, uint32_t en) {
    asm volatile(
        "{\n\t.reg .pred p;\n\t"
        "setp.ne.u32 p, %4, 0;\n\t"
        "tcgen05.mma.cta_group::1.kind::tf32 [%0], %1, %2, %3, p;\n\t}"
        :: "r"(d), "l"(ad), "l"(bd), "r"(idesc), "r"(en) : "memory");
}
// K-major SW128 smem descriptor (LBO=1, SBO=64, version=1, layout=SW128)
__device__ __forceinline__ uint64_t mkdesc(uint32_t addr) {
    return (uint64_t)((addr >> 4) & 0x3FFF)
         | (1ull << 16) | (64ull << 32) | (1ull << 46) | (2ull << 61);
}
#define TC_LD_X32(r, tm) \
    asm volatile( \
        "tcgen05.ld.sync.aligned.32x32b.x32.b32 " \
        "{%0, %1, %2, %3, %4, %5, %6, %7, " \
        " %8, %9, %10, %11, %12, %13, %14, %15, " \
        " %16, %17, %18, %19, %20, %21, %22, %23, " \
        " %24, %25, %26, %27, %28, %29, %30, %31}, [%32];" \
        : "=r"((r)[0]),  "=r"((r)[1]),  "=r"((r)[2]),  "=r"((r)[3]), \
          "=r"((r)[4]),  "=r"((r)[5]),  "=r"((r)[6]),  "=r"((r)[7]), \
          "=r"((r)[8]),  "=r"((r)[9]),  "=r"((r)[10]), "=r"((r)[11]), \
          "=r"((r)[12]), "=r"((r)[13]), "=r"((r)[14]), "=r"((r)[15]), \
          "=r"((r)[16]), "=r"((r)[17]), "=r"((r)[18]), "=r"((r)[19]), \
          "=r"((r)[20]), "=r"((r)[21]), "=r"((r)[22]), "=r"((r)[23]), \
          "=r"((r)[24]), "=r"((r)[25]), "=r"((r)[26]), "=r"((r)[27]), \
          "=r"((r)[28]), "=r"((r)[29]), "=r"((r)[30]), "=r"((r)[31]) \
        : "r"(tm))
#endif  // HAS_TC

// ---------------- router ------------------------------------------------------
__global__ void __launch_bounds__(256) router_kernel(const float* __restrict__ x,
                                                     const float* __restrict__ Wg) {
    int wid  = threadIdx.x >> 5;
    int lane = threadIdx.x & 31;
    int t = blockIdx.x * 8 + wid;
    if (t >= NT) return;

    float acc[NE];
#pragma unroll
    for (int e = 0; e < NE; e++) acc[e] = 0.f;

    const float4* xr = reinterpret_cast<const float4*>(x + (size_t)t * DM);
#pragma unroll 4
    for (int i = lane; i < DM / 4; i += 32) {
        float4 v = xr[i];
        int d = i * 4;
#pragma unroll
        for (int e = 0; e < NE; e++) {
            acc[e] += v.x * Wg[(d + 0) * NE + e];
            acc[e] += v.y * Wg[(d + 1) * NE + e];
            acc[e] += v.z * Wg[(d + 2) * NE + e];
            acc[e] += v.w * Wg[(d + 3) * NE + e];
        }
    }
#pragma unroll
    for (int e = 0; e < NE; e++)
#pragma unroll
        for (int off = 16; off > 0; off >>= 1)
            acc[e] += __shfl_xor_sync(0xffffffffu, acc[e], off);

    if (lane == 0) {
        float l0 = -1e30f; int e0 = 0;
#pragma unroll
        for (int e = 0; e < NE; e++) if (acc[e] > l0) { l0 = acc[e]; e0 = e; }
        float l1 = -1e30f; int e1 = 0;
#pragma unroll
        for (int e = 0; e < NE; e++) if (e != e0 && acc[e] > l1) { l1 = acc[e]; e1 = e; }
        float w0 = 1.f / (1.f + __expf(l1 - l0));
        g_te[2 * t]     = e0;  g_te[2 * t + 1] = e1;
        g_tw[2 * t]     = w0;  g_tw[2 * t + 1] = 1.f - w0;
    }
}

// ---------------- ordered capacity scan --------------------------------------
__global__ void __launch_bounds__(256) scan_kernel() {
    __shared__ int s_run[NE];
    __shared__ int s_wtot[8][NE];
    int tid  = threadIdx.x;
    int wid  = tid >> 5;
    int lane = tid & 31;
    if (tid < NE) s_run[tid] = 0;
    __syncthreads();

    for (int base = 0; base < TK; base += 256) {
        int i = base + tid;
        int e = g_te[i];
        int rank = 0;
#pragma unroll
        for (int ee = 0; ee < NE; ee++) {
            unsigned m = __ballot_sync(0xffffffffu, e == ee);
            if (e == ee) rank = __popc(m & ((1u << lane) - 1u));
            if (lane == 0) s_wtot[wid][ee] = __popc(m);
        }
        __syncthreads();
        int off = s_run[e];
        for (int w = 0; w < wid; w++) off += s_wtot[w][e];
        int pos = off + rank;
        if (pos < CAPACITY) {
            g_src[e * CAPACITY + pos] = i >> 1;
            g_cidx[i] = e * CAPACITY + pos;
            g_cw[i]   = g_tw[i];
        } else {
            g_cidx[i] = 0;
            g_cw[i]   = 0.f;
        }
        __syncthreads();
        if (tid < NE) {
            int tot = 0;
#pragma unroll
            for (int w = 0; w < 8; w++) tot += s_wtot[w][tid];
            s_run[tid] += tot;
        }
        __syncthreads();
    }
    if (tid < NE) g_cnt[tid] = min(s_run[tid], CAPACITY);
    __syncthreads();
    for (int idx = tid; idx < NE * CAPACITY; idx += 256) {
        int e = idx / CAPACITY, c = idx % CAPACITY;
        if (c >= min(s_run[e], CAPACITY)) g_src[idx] = 0;
    }
}

// ---------------- prep: tf32-round x, transpose+round W ----------------------
__global__ void __launch_bounds__(256) convert_x_kernel(const float* __restrict__ x) {
    size_t i = ((size_t)blockIdx.x * 256 + threadIdx.x) * 4;
    float4 v = *reinterpret_cast<const float4*>(x + i);
    v.x = to_tf32(v.x); v.y = to_tf32(v.y); v.z = to_tf32(v.z); v.w = to_tf32(v.w);
    *reinterpret_cast<float4*>(g_xr + i) = v;
}

__global__ void __launch_bounds__(256) transpose_w_kernel(const float* __restrict__ W,
                                                          float* __restrict__ Wt,
                                                          int KD, int ND) {
    __shared__ float t[32][33];
    int e = blockIdx.z;
    int n0 = blockIdx.x * 32, k0 = blockIdx.y * 32;
    const float* src = W + (size_t)e * KD * ND;
    float* dst = Wt + (size_t)e * KD * ND;
    int tx = threadIdx.x & 31, ty = threadIdx.x >> 5;   // 32 x 8
#pragma unroll
    for (int r = 0; r < 32; r += 8)
        t[ty + r][tx] = src[(size_t)(k0 + ty + r) * ND + n0 + tx];
    __syncthreads();
#pragma unroll
    for (int r = 0; r < 32; r += 8)
        dst[(size_t)(n0 + ty + r) * KD + k0 + tx] = to_tf32(t[tx][ty + r]);
}

// ---------------- grouped GEMM (tcgen05 or wmma fallback) --------------------
#define BM 128
#define BN 256
#define BKC 32
#define STAGES 4
#define STAGE_BYTES (BM*128 + BN*128)     // 49152
#define SMEM_SZ (1088 + STAGES*STAGE_BYTES)

// idesc: c=F32(1<<4), a=TF32(2<<7), b=TF32(2<<10), N=256 (32<<17), M=128 (8<<24)
#define IDESC ((1u<<4) | (2u<<7) | (2u<<10) | ((BN/8)<<17) | ((BM/16)<<24))

// WHICH==1: h = gelu(buf @ W1);  WHICH==2: y = h @ W2
// Wsrc: base of full un-transposed weight tensor [E, K, N] (fallback path only).
template <int WHICH>
__global__ void __launch_bounds__(256, 1) moe_gemm_tc(const float* __restrict__ Wsrc) {
    constexpr int Kd = (WHICH == 1) ? DM : DFF;
    constexpr int Nd = (WHICH == 1) ? DFF : DM;

    int e  = blockIdx.z;
    int m0 = blockIdx.x * BM;
    int n0 = blockIdx.y * BN;
    if (m0 >= g_cnt[e]) return;

    extern __shared__ char smem[];
    int tid = threadIdx.x, wid = tid >> 5, lane = tid & 31;

#if HAS_TC
    // ================= tcgen05 SS tf32 pipeline ==============================
    (void)Wsrc;
    constexpr int NCH = Kd / BKC;
    uint32_t sb = smem_u32(smem);
    uint32_t tmp_addr = sb;                 // tcgen05.alloc result
    uint32_t mb = sb + 16;                  // 4 mbarriers
    uint32_t stage0 = (sb + 64 + 1023) & ~1023u;

    const char* aptr[4]; uint32_t dsoA[4];
#pragma unroll
    for (int it = 0; it < 4; it++) {
        int idx = tid + it * 256;
        int row = idx >> 3, seg = idx & 7;
        const float* p;
        if (WHICH == 1) p = g_xr + (size_t)g_src[e * CAPACITY + m0 + row] * Kd;
        else            p = g_h  + (size_t)(e * CAPACITY + m0 + row) * Kd;
        aptr[it] = (const char*)p + seg * 16;
        dsoA[it] = swz((uint32_t)(row * 128 + seg * 16));
    }
    const float* brow = ((WHICH == 1) ? g_w1t : g_w2t) + ((size_t)e * Nd + n0) * Kd;
    const char* bptr[8]; uint32_t dsoB[8];
#pragma unroll
    for (int it = 0; it < 8; it++) {
        int idx = tid + it * 256;
        int row = idx >> 3, seg = idx & 7;
        bptr[it] = (const char*)(brow + (size_t)row * Kd) + seg * 16;
        dsoB[it] = (uint32_t)(BM * 128) + swz((uint32_t)(row * 128 + seg * 16));
    }

    if (tid < 4) mbar_init(mb + tid * 8);
    if (wid == 0) TC_ALLOC(tmp_addr, 256);
    __syncthreads();
    uint32_t tmem;
    asm volatile("ld.shared.b32 %0, [%1];" : "=r"(tmem) : "r"(tmp_addr));

    auto load_chunk = [&](int sp, int k0c) {
        uint32_t st = stage0 + sp * STAGE_BYTES;
        uint32_t kb = (uint32_t)k0c * 4;
#pragma unroll
        for (int it = 0; it < 4; it++) cp16(st + dsoA[it], aptr[it] + kb);
#pragma unroll
        for (int it = 0; it < 8; it++) cp16(st + dsoB[it], bptr[it] + kb);
    };

#pragma unroll
    for (int p = 0; p < 3; p++) { load_chunk(p, p * BKC); CP_COMMIT(); }

    uint32_t phbits = 0;
    for (int i = 0; i < NCH; i++) {
        int s = i & 3;
        int pre = i + 3;
        if (pre < NCH) {
            int sp = pre & 3;
            if (i >= 1) {
                mbar_wait(mb + sp * 8, (phbits >> sp) & 1u);
                phbits ^= 1u << sp;
            }
            load_chunk(sp, pre * BKC);
        }
        CP_COMMIT();
        CP_WAIT3();
        __syncthreads();
        if (wid == 0) {
            FENCE_ASYNC_SHARED();
            if (elect_one()) {
                uint64_t ad = mkdesc(stage0 + s * STAGE_BYTES);
                uint64_t bd = mkdesc(stage0 + s * STAGE_BYTES + BM * 128);
#pragma unroll
                for (int st = 0; st < 4; st++)
                    mma_tf32_ss(tmem, ad + st * 2, bd + st * 2, IDESC,
                                (i > 0) || (st > 0));
                TC_COMMIT(mb + s * 8);
            }
        }
    }

    int sl = (NCH - 1) & 3;
    mbar_wait(mb + sl * 8, (phbits >> sl) & 1u);
    TC_FENCE_AFTER();

    int part = wid & 3, half = wid >> 2;
    size_t row = (size_t)(e * CAPACITY + m0 + part * 32 + lane);
    float* outp = ((WHICH == 1) ? g_h : g_y) + row * Nd + n0 + half * 128;
#pragma unroll
    for (int b = 0; b < 4; b++) {
        uint32_t u[32];
        TC_LD_X32(u, tmem + half * 128 + b * 32);
        TC_WAIT_LD();
#pragma unroll
        for (int c = 0; c < 32; c += 4) {
            float f0 = __uint_as_float(u[c + 0]);
            float f1 = __uint_as_float(u[c + 1]);
            float f2 = __uint_as_float(u[c + 2]);
            float f3 = __uint_as_float(u[c + 3]);
            if (WHICH == 1) {
                f0 = to_tf32(gelu_tanh(f0)); f1 = to_tf32(gelu_tanh(f1));
                f2 = to_tf32(gelu_tanh(f2)); f3 = to_tf32(gelu_tanh(f3));
            }
            float4 v = make_float4(f0, f1, f2, f3);
            *reinterpret_cast<float4*>(outp + b * 32 + c) = v;
        }
    }
    TC_FENCE_BEFORE();
    __syncthreads();
    if (wid == 0) {
        TC_RELINQ();
        TC_DEALLOC(tmem, 256);
    }
#else
    // ================= tf32 wmma fallback (same tile/grid) ====================
    using namespace nvcuda;
    constexpr int BK = 16;
    constexpr int NCH = Kd / BK;
    const float* We = Wsrc + (size_t)e * Kd * Nd;        // expert's [K, N] weights
    // carve dynamic smem
    float* As = reinterpret_cast<float*>(smem);                    // [2][BM][BK+4]
    float* Bs = As + 2 * BM * (BK + 4);                            // [2][BK][BN+8]
    const float** s_arow = reinterpret_cast<const float**>(Bs + 2 * BK * (BN + 8));

    for (int r = tid; r < BM; r += 256) {
        if (WHICH == 1) {
            int tok = g_src[e * CAPACITY + m0 + r];
            s_arow[r] = g_xr + (size_t)tok * Kd;
        } else {
            s_arow[r] = g_h + (size_t)(e * CAPACITY + m0 + r) * Kd;
        }
    }
    __syncthreads();

    auto Aat = [&](int buf, int r, int c) -> float& { return As[(buf * BM + r) * (BK + 4) + c]; };
    auto Bat = [&](int buf, int r, int c) -> float& { return Bs[(buf * BK + r) * (BN + 8) + c]; };

    auto loadA = [&](int buf, int k0) {
#pragma unroll
        for (int it = 0; it < 2; it++) {
            int idx = tid * 2 + it;
            int r = idx >> 2, q = idx & 3;
            float4 v = *reinterpret_cast<const float4*>(s_arow[r] + k0 + q * 4);
            *reinterpret_cast<float4*>(&Aat(buf, r, q * 4)) = v;
        }
    };
    auto loadB = [&](int buf, int k0) {
#pragma unroll
        for (int it = 0; it < 4; it++) {
            int idx = tid + it * 256;
            int r = idx >> 6, c = idx & 63;
            float4 v = *reinterpret_cast<const float4*>(We + (size_t)(k0 + r) * Nd + n0 + c * 4);
            *reinterpret_cast<float4*>(&Bat(buf, r, c * 4)) = v;
        }
    };

    typedef wmma::fragment<wmma::matrix_a, 16, 16, 8, wmma::precision::tf32, wmma::row_major> FragA;
    typedef wmma::fragment<wmma::matrix_b, 16, 16, 8, wmma::precision::tf32, wmma::row_major> FragB;
    typedef wmma::fragment<wmma::accumulator, 16, 16, 8, float> FragC;

    FragC acc[4][4];
#pragma unroll
    for (int i = 0; i < 4; i++)
#pragma unroll
        for (int j = 0; j < 4; j++) wmma::fill_fragment(acc[i][j], 0.f);

    int wm = wid >> 2;     // 0..1  -> 64-row half
    int wn = wid & 3;      // 0..3  -> 64-col quarter

    loadA(0, 0);
    loadB(0, 0);
    __syncthreads();

    for (int ks = 0; ks < NCH; ks++) {
        int cur = ks & 1;
        if (ks + 1 < NCH) { loadA(cur ^ 1, (ks + 1) * BK); loadB(cur ^ 1, (ks + 1) * BK); }
#pragma unroll
        for (int kk = 0; kk < 2; kk++) {
            FragA af[4];
            FragB bf[4];
#pragma unroll
            for (int i = 0; i < 4; i++)
                wmma::load_matrix_sync(af[i], &Aat(cur, wm * 64 + i * 16, kk * 8), BK + 4);
#pragma unroll
            for (int j = 0; j < 4; j++) {
                wmma::load_matrix_sync(bf[j], &Bat(cur, kk * 8, wn * 64 + j * 16), BN + 8);
#pragma unroll
                for (int t = 0; t < bf[j].num_elements; t++)
                    bf[j].x[t] = wmma::__float_to_tf32(bf[j].x[t]);
            }
#pragma unroll
            for (int i = 0; i < 4; i++)
#pragma unroll
                for (int j = 0; j < 4; j++)
                    wmma::mma_sync(acc[i][j], af[i], bf[j], acc[i][j]);
        }
        __syncthreads();
    }

    float* Cb = ((WHICH == 1) ? g_h : g_y) + (size_t)(e * CAPACITY + m0) * Nd + n0;
#pragma unroll
    for (int i = 0; i < 4; i++)
#pragma unroll
        for (int j = 0; j < 4; j++) {
            if (WHICH == 1) {
#pragma unroll
                for (int t = 0; t < acc[i][j].num_elements; t++)
                    acc[i][j].x[t] = to_tf32(gelu_tanh(acc[i][j].x[t]));
            }
            wmma::store_matrix_sync(Cb + (size_t)(wm * 64 + i * 16) * Nd + wn * 64 + j * 16,
                                    acc[i][j], Nd, wmma::mem_row_major);
        }
#endif
}

// ---------------- combine -----------------------------------------------------
__global__ void __launch_bounds__(256) combine_kernel(float* __restrict__ out) {
    int t   = blockIdx.x;
    int tid = threadIdx.x;
    int i0 = g_cidx[2 * t],     i1 = g_cidx[2 * t + 1];
    float w0 = g_cw[2 * t],     w1 = g_cw[2 * t + 1];
    const float4* y0 = reinterpret_cast<const float4*>(g_y + (size_t)i0 * DM);
    const float4* y1 = reinterpret_cast<const float4*>(g_y + (size_t)i1 * DM);
    float4 a = y0[tid], b = y1[tid];
    float4 r;
    r.x = w0 * a.x + w1 * b.x;
    r.y = w0 * a.y + w1 * b.y;
    r.z = w0 * a.z + w1 * b.z;
    r.w = w0 * a.w + w1 * b.w;
    reinterpret_cast<float4*>(out + (size_t)t * DM)[tid] = r;
}

// ---------------- launch ------------------------------------------------------
extern "C" void kernel_launch(void* const* d_in, const int* in_sizes, int n_in,
                              void* d_out, int out_size) {
    const float* x  = (const float*)d_in[0];   // [T, D]
    const float* Wg = (const float*)d_in[1];   // [D, E]
    const float* W1 = (const float*)d_in[2];   // [E, D, H]
    const float* W2 = (const float*)d_in[3];   // [E, H, D]
    float* out = (float*)d_out;                // [T, D]

    cudaFuncSetAttribute(moe_gemm_tc<1>, cudaFuncAttributeMaxDynamicSharedMemorySize, SMEM_SZ);
    cudaFuncSetAttribute(moe_gemm_tc<2>, cudaFuncAttributeMaxDynamicSharedMemorySize, SMEM_SZ);

    router_kernel<<<NT / 8, 256>>>(x, Wg);
    convert_x_kernel<<<(NT * DM) / 1024, 256>>>(x);
    {
        float* w1t; cudaGetSymbolAddress((void**)&w1t, g_w1t);
        transpose_w_kernel<<<dim3(DFF / 32, DM / 32, NE), 256>>>(W1, w1t, DM, DFF);
    }
    {
        float* w2t; cudaGetSymbolAddress((void**)&w2t, g_w2t);
        transpose_w_kernel<<<dim3(DM / 32, DFF / 32, NE), 256>>>(W2, w2t, DFF, DM);
    }
    scan_kernel<<<1, 256>>>();
    moe_gemm_tc<1><<<dim3(CAPACITY / BM, DFF / BN, NE), 256, SMEM_SZ>>>(W1);
    moe_gemm_tc<2><<<dim3(CAPACITY / BM, DM  / BN, NE), 256, SMEM_SZ>>>(W2);
    combine_kernel<<<NT, 256>>>(out);
}

// round 7
// speedup vs baseline: 5.3731x; 1.0646x over previous
#include <cuda_runtime.h>
#include <mma.h>
#include <math.h>
#include <stdint.h>

#define NE 7
#define TOPK 2
#define CAPACITY 3072
#define DM 1024
#define DFF 4096
#define NT 8192
#define TK (NT*TOPK)

#if defined(__CUDA_ARCH__) && defined(__CUDA_ARCH_FEAT_SM103_ALL)
#define HAS_TC 1
#else
#define HAS_TC 0
#endif

// ---------------- scratch (device globals; no allocations allowed) ----------
__device__ int   g_te[TK];
__device__ float g_tw[TK];
__device__ int   g_src[NE*CAPACITY];
__device__ int   g_cnt[NE];
__device__ int   g_cidx[TK];
__device__ float g_cw[TK];
__device__ float g_xr[(size_t)NT*DM];                    // tf32-rounded x
__device__ float g_w1t[(size_t)NE*(size_t)DFF*DM];       // W1^T  [e][n][k] tf32
__device__ float g_w2t[(size_t)NE*(size_t)DM*DFF];       // W2^T  [e][n][k] tf32
__device__ float g_h[(size_t)NE*CAPACITY*DFF];           // gelu(buf@W1), tf32-rounded
__device__ float g_y[(size_t)NE*CAPACITY*DM];            // h@W2

// ---------------- common helpers ---------------------------------------------
__device__ __forceinline__ float to_tf32(float f) {
    float r; asm("cvt.rna.tf32.f32 %0, %1;" : "=f"(r) : "f"(f)); return r;
}
__device__ __forceinline__ float gelu_tanh(float v) {
    float c = 0.7978845608028654f * (v + 0.044715f * v * v * v);
    return 0.5f * v * (1.f + tanhf(c));
}
__device__ __forceinline__ uint32_t smem_u32(const void* p) {
    uint32_t a;
    asm("{ .reg .u64 t; cvta.to.shared.u64 t, %1; cvt.u32.u64 %0, t; }" : "=r"(a) : "l"(p));
    return a;
}

#if HAS_TC
// ---------------- tcgen05-only PTX helpers -----------------------------------
__device__ __forceinline__ uint32_t elect_one() {
    uint32_t p;
    asm volatile("{\n\t.reg .pred p;\n\telect.sync _|p, 0xFFFFFFFF;\n\tselp.b32 %0, 1, 0, p;\n\t}" : "=r"(p));
    return p;
}
__device__ __forceinline__ uint32_t swz(uint32_t b) { return b ^ ((b >> 3) & 0x70); }

__device__ __forceinline__ void cp16(uint32_t dst, const void* src) {
    asm volatile("cp.async.cg.shared.global [%0], [%1], 16;" :: "r"(dst), "l"(src) : "memory");
}
#define CP_COMMIT() asm volatile("cp.async.commit_group;" ::: "memory")
#define CP_WAIT2()  asm volatile("cp.async.wait_group 2;" ::: "memory")

__device__ __forceinline__ void mbar_init(uint32_t a) {
    asm volatile("mbarrier.init.shared.b64 [%0], %1;" :: "r"(a), "r"(1u) : "memory");
}
__device__ __forceinline__ void mbar_wait(uint32_t a, uint32_t parity) {
    asm volatile(
        "{\n\t.reg .pred P;\n\t"
        "WAITLOOP_%=:\n\t"
        "mbarrier.try_wait.parity.acquire.cta.shared::cta.b64 P, [%0], %1, 0x989680;\n\t"
        "@P bra.uni WDONE_%=;\n\t"
        "bra.uni WAITLOOP_%=;\n\t"
        "WDONE_%=:\n\t}"
        :: "r"(a), "r"(parity) : "memory");
}

#define TC_ALLOC(smaddr, n)  asm volatile("tcgen05.alloc.cta_group::1.sync.aligned.shared::cta.b32 [%0], %1;" :: "r"(smaddr), "r"((uint32_t)(n)) : "memory")
#define TC_DEALLOC(tm, n)    asm volatile("tcgen05.dealloc.cta_group::1.sync.aligned.b32 %0, %1;" :: "r"(tm), "r"((uint32_t)(n)))
#define TC_RELINQ()          asm volatile("tcgen05.relinquish_alloc_permit.cta_group::1.sync.aligned;")
#define TC_COMMIT(mb)        asm volatile("tcgen05.commit.cta_group::1.mbarrier::arrive::one.shared::cluster.b64 [%0];" :: "r"(mb) : "memory")
#define TC_WAIT_LD()         asm volatile("tcgen05.wait::ld.sync.aligned;" ::: "memory")
#define TC_FENCE_BEFORE()    asm volatile("tcgen05.fence::before_thread_sync;" ::: "memory")
#define TC_FENCE_AFTER()     asm volatile("tcgen05.fence::after_thread_sync;" ::: "memory")
#define FENCE_ASYNC_SHARED() asm volatile("fence.proxy.async.shared::cta;" ::: "memory")

__device__ __forceinline__ void mma_tf32_ss(uint32_t d, uint64_t ad, uint64_t bd,
                                            uint32_t idesc, uint32_t en) {
    asm volatile(
        "{\n\t.reg .pred p;\n\t"
        "setp.ne.u32 p, %4, 0;\n\t"
        "tcgen05.mma.cta_group::1.kind::tf32 [%0], %1, %2, %3, p;\n\t}"
        :: "r"(d), "l"(ad), "l"(bd), "r"(idesc), "r"(en) : "memory");
}
// K-major SW128 smem descriptor (LBO=1, SBO=64, version=1, layout=SW128)
__device__ __forceinline__ uint64_t mkdesc(uint32_t addr) {
    return (uint64_t)((addr >> 4) & 0x3FFF)
         | (1ull << 16) | (64ull << 32) | (1ull << 46) | (2ull << 61);
}
#define TC_LD_X32(r, tm) \
    asm volatile( \
        "tcgen05.ld.sync.aligned.32x32b.x32.b32 " \
        "{%0, %1, %2, %3, %4, %5, %6, %7, " \
        " %8, %9, %10, %11, %12, %13, %14, %15, " \
        " %16, %17, %18, %19, %20, %21, %22, %23, " \
        " %24, %25, %26, %27, %28, %29, %30, %31}, [%32];" \
        : "=r"((r)[0]),  "=r"((r)[1]),  "=r"((r)[2]),  "=r"((r)[3]), \
          "=r"((r)[4]),  "=r"((r)[5]),  "=r"((r)[6]),  "=r"((r)[7]), \
          "=r"((r)[8]),  "=r"((r)[9]),  "=r"((r)[10]), "=r"((r)[11]), \
          "=r"((r)[12]), "=r"((r)[13]), "=r"((r)[14]), "=r"((r)[15]), \
          "=r"((r)[16]), "=r"((r)[17]), "=r"((r)[18]), "=r"((r)[19]), \
          "=r"((r)[20]), "=r"((r)[21]), "=r"((r)[22]), "=r"((r)[23]), \
          "=r"((r)[24]), "=r"((r)[25]), "=r"((r)[26]), "=r"((r)[27]), \
          "=r"((r)[28]), "=r"((r)[29]), "=r"((r)[30]), "=r"((r)[31]) \
        : "r"(tm))
#endif  // HAS_TC

// ---------------- router ------------------------------------------------------
__global__ void __launch_bounds__(256) router_kernel(const float* __restrict__ x,
                                                     const float* __restrict__ Wg) {
    int wid  = threadIdx.x >> 5;
    int lane = threadIdx.x & 31;
    int t = blockIdx.x * 8 + wid;
    if (t >= NT) return;

    float acc[NE];
#pragma unroll
    for (int e = 0; e < NE; e++) acc[e] = 0.f;

    const float4* xr = reinterpret_cast<const float4*>(x + (size_t)t * DM);
#pragma unroll 4
    for (int i = lane; i < DM / 4; i += 32) {
        float4 v = xr[i];
        int d = i * 4;
#pragma unroll
        for (int e = 0; e < NE; e++) {
            acc[e] += v.x * Wg[(d + 0) * NE + e];
            acc[e] += v.y * Wg[(d + 1) * NE + e];
            acc[e] += v.z * Wg[(d + 2) * NE + e];
            acc[e] += v.w * Wg[(d + 3) * NE + e];
        }
    }
#pragma unroll
    for (int e = 0; e < NE; e++)
#pragma unroll
        for (int off = 16; off > 0; off >>= 1)
            acc[e] += __shfl_xor_sync(0xffffffffu, acc[e], off);

    if (lane == 0) {
        float l0 = -1e30f; int e0 = 0;
#pragma unroll
        for (int e = 0; e < NE; e++) if (acc[e] > l0) { l0 = acc[e]; e0 = e; }
        float l1 = -1e30f; int e1 = 0;
#pragma unroll
        for (int e = 0; e < NE; e++) if (e != e0 && acc[e] > l1) { l1 = acc[e]; e1 = e; }
        float w0 = 1.f / (1.f + __expf(l1 - l0));
        g_te[2 * t]     = e0;  g_te[2 * t + 1] = e1;
        g_tw[2 * t]     = w0;  g_tw[2 * t + 1] = 1.f - w0;
    }
}

// ---------------- ordered capacity scan --------------------------------------
__global__ void __launch_bounds__(256) scan_kernel() {
    __shared__ int s_run[NE];
    __shared__ int s_wtot[8][NE];
    int tid  = threadIdx.x;
    int wid  = tid >> 5;
    int lane = tid & 31;
    if (tid < NE) s_run[tid] = 0;
    __syncthreads();

    for (int base = 0; base < TK; base += 256) {
        int i = base + tid;
        int e = g_te[i];
        int rank = 0;
#pragma unroll
        for (int ee = 0; ee < NE; ee++) {
            unsigned m = __ballot_sync(0xffffffffu, e == ee);
            if (e == ee) rank = __popc(m & ((1u << lane) - 1u));
            if (lane == 0) s_wtot[wid][ee] = __popc(m);
        }
        __syncthreads();
        int off = s_run[e];
        for (int w = 0; w < wid; w++) off += s_wtot[w][e];
        int pos = off + rank;
        if (pos < CAPACITY) {
            g_src[e * CAPACITY + pos] = i >> 1;
            g_cidx[i] = e * CAPACITY + pos;
            g_cw[i]   = g_tw[i];
        } else {
            g_cidx[i] = 0;
            g_cw[i]   = 0.f;
        }
        __syncthreads();
        if (tid < NE) {
            int tot = 0;
#pragma unroll
            for (int w = 0; w < 8; w++) tot += s_wtot[w][tid];
            s_run[tid] += tot;
        }
        __syncthreads();
    }
    if (tid < NE) g_cnt[tid] = min(s_run[tid], CAPACITY);
    __syncthreads();
    for (int idx = tid; idx < NE * CAPACITY; idx += 256) {
        int e = idx / CAPACITY, c = idx % CAPACITY;
        if (c >= min(s_run[e], CAPACITY)) g_src[idx] = 0;
    }
}

// ---------------- prep: tf32-round x, transpose+round W ----------------------
__global__ void __launch_bounds__(256) convert_x_kernel(const float* __restrict__ x) {
    size_t i = ((size_t)blockIdx.x * 256 + threadIdx.x) * 4;
    float4 v = *reinterpret_cast<const float4*>(x + i);
    v.x = to_tf32(v.x); v.y = to_tf32(v.y); v.z = to_tf32(v.z); v.w = to_tf32(v.w);
    *reinterpret_cast<float4*>(g_xr + i) = v;
}

__global__ void __launch_bounds__(256) transpose_w_kernel(const float* __restrict__ W,
                                                          float* __restrict__ Wt,
                                                          int KD, int ND) {
    __shared__ float t[32][33];
    int e = blockIdx.z;
    int n0 = blockIdx.x * 32, k0 = blockIdx.y * 32;
    const float* src = W + (size_t)e * KD * ND;
    float* dst = Wt + (size_t)e * KD * ND;
    int tx = threadIdx.x & 31, ty = threadIdx.x >> 5;   // 32 x 8
#pragma unroll
    for (int r = 0; r < 32; r += 8)
        t[ty + r][tx] = src[(size_t)(k0 + ty + r) * ND + n0 + tx];
    __syncthreads();
#pragma unroll
    for (int r = 0; r < 32; r += 8)
        dst[(size_t)(n0 + ty + r) * KD + k0 + tx] = to_tf32(t[tx][ty + r]);
}

// ---------------- grouped GEMM (tcgen05 or wmma fallback) --------------------
#define BMP 256                           // rows per CTA (two 128-row MMA tiles)
#define BN 256
#define BKC 32
#define STAGES 3
#define STAGE_BYTES (BMP*128 + BN*128)    // A 32KB + B 32KB = 65536
#define SMEM_SZ (1088 + STAGES*STAGE_BYTES)

// idesc: c=F32(1<<4), a=TF32(2<<7), b=TF32(2<<10), N=256 (32<<17), M=128 (8<<24)
#define IDESC ((1u<<4) | (2u<<7) | (2u<<10) | ((BN/8)<<17) | ((128/16)<<24))

// WHICH==1: h = gelu(buf @ W1);  WHICH==2: y = h @ W2
// Wsrc: base of full un-transposed weight tensor [E, K, N] (fallback path only).
template <int WHICH>
__global__ void __launch_bounds__(256, 1) moe_gemm_tc(const float* __restrict__ Wsrc) {
    constexpr int Kd = (WHICH == 1) ? DM : DFF;
    constexpr int Nd = (WHICH == 1) ? DFF : DM;

    int e  = blockIdx.z;
    int m0 = blockIdx.x * BMP;
    int n0 = blockIdx.y * BN;
    if (m0 >= g_cnt[e]) return;

    extern __shared__ char smem[];
    int tid = threadIdx.x, wid = tid >> 5, lane = tid & 31;

#if HAS_TC
    // ================= tcgen05 SS tf32 pipeline, 2 M-tiles share B ===========
    (void)Wsrc;
    constexpr int NCH = Kd / BKC;
    uint32_t sb = smem_u32(smem);
    uint32_t tmp_addr = sb;                 // tcgen05.alloc result
    uint32_t mb = sb + 16;                  // 3 mbarriers
    uint32_t stage0 = (sb + 64 + 1023) & ~1023u;

    // A: 256 rows x 128B per chunk -> 8 cp16 per thread
    const char* aptr[8]; uint32_t dsoA[8];
#pragma unroll
    for (int it = 0; it < 8; it++) {
        int idx = tid + it * 256;
        int row = idx >> 3, seg = idx & 7;
        const float* p;
        if (WHICH == 1) p = g_xr + (size_t)g_src[e * CAPACITY + m0 + row] * Kd;
        else            p = g_h  + (size_t)(e * CAPACITY + m0 + row) * Kd;
        aptr[it] = (const char*)p + seg * 16;
        dsoA[it] = swz((uint32_t)(row * 128 + seg * 16));
    }
    // B: 256 rows x 128B per chunk -> 8 cp16 per thread
    const float* brow = ((WHICH == 1) ? g_w1t : g_w2t) + ((size_t)e * Nd + n0) * Kd;
    const char* bptr[8]; uint32_t dsoB[8];
#pragma unroll
    for (int it = 0; it < 8; it++) {
        int idx = tid + it * 256;
        int row = idx >> 3, seg = idx & 7;
        bptr[it] = (const char*)(brow + (size_t)row * Kd) + seg * 16;
        dsoB[it] = (uint32_t)(BMP * 128) + swz((uint32_t)(row * 128 + seg * 16));
    }

    if (tid < STAGES) mbar_init(mb + tid * 8);
    if (wid == 0) TC_ALLOC(tmp_addr, 512);
    __syncthreads();
    uint32_t tmem;
    asm volatile("ld.shared.b32 %0, [%1];" : "=r"(tmem) : "r"(tmp_addr));

    auto load_chunk = [&](int sp, int k0c) {
        uint32_t st = stage0 + sp * STAGE_BYTES;
        uint32_t kb = (uint32_t)k0c * 4;
#pragma unroll
        for (int it = 0; it < 8; it++) cp16(st + dsoA[it], aptr[it] + kb);
#pragma unroll
        for (int it = 0; it < 8; it++) cp16(st + dsoB[it], bptr[it] + kb);
    };

    // preload 2 chunks
#pragma unroll
    for (int p = 0; p < 2; p++) { load_chunk(p, p * BKC); CP_COMMIT(); }

    uint32_t phbits = 0;
    for (int i = 0; i < NCH; i++) {
        int s = i % 3;
        int pre = i + 2;
        if (pre < NCH) {
            int sp = pre % 3;
            if (i >= 1) {               // stage sp was consumed by MMA of chunk i-1
                mbar_wait(mb + sp * 8, (phbits >> sp) & 1u);
                phbits ^= 1u << sp;
            }
            load_chunk(sp, pre * BKC);
        }
        CP_COMMIT();                    // one group per iteration (may be empty)
        CP_WAIT2();                     // chunk i's group retired
        __syncthreads();
        if (wid == 0) {
            FENCE_ASYNC_SHARED();
            if (elect_one()) {
                uint64_t ad0 = mkdesc(stage0 + s * STAGE_BYTES);
                uint64_t ad1 = ad0 + 1024;                       // +128 rows * 128B / 16
                uint64_t bd  = mkdesc(stage0 + s * STAGE_BYTES + BMP * 128);
#pragma unroll
                for (int st = 0; st < 4; st++) {
                    uint32_t en = (i > 0) || (st > 0);
                    mma_tf32_ss(tmem,       ad0 + st * 2, bd + st * 2, IDESC, en);
                    mma_tf32_ss(tmem + 256, ad1 + st * 2, bd + st * 2, IDESC, en);
                }
                TC_COMMIT(mb + s * 8);
            }
        }
    }

    // wait for final MMA batch (prior batches complete in order)
    int sl = (NCH - 1) % 3;
    mbar_wait(mb + sl * 8, (phbits >> sl) & 1u);
    TC_FENCE_AFTER();

    // epilogue: warps 0-3 -> M-tile 0 (D at tmem+0), warps 4-7 -> M-tile 1 (tmem+256)
    int part = wid & 3, tb = wid >> 2;
    size_t row = (size_t)(e * CAPACITY + m0 + tb * 128 + part * 32 + lane);
    float* outp = ((WHICH == 1) ? g_h : g_y) + row * Nd + n0;
    uint32_t dbase = tmem + tb * 256;
#pragma unroll
    for (int b = 0; b < 8; b++) {
        uint32_t u[32];
        TC_LD_X32(u, dbase + b * 32);
        TC_WAIT_LD();
#pragma unroll
        for (int c = 0; c < 32; c += 4) {
            float f0 = __uint_as_float(u[c + 0]);
            float f1 = __uint_as_float(u[c + 1]);
            float f2 = __uint_as_float(u[c + 2]);
            float f3 = __uint_as_float(u[c + 3]);
            if (WHICH == 1) {
                f0 = to_tf32(gelu_tanh(f0)); f1 = to_tf32(gelu_tanh(f1));
                f2 = to_tf32(gelu_tanh(f2)); f3 = to_tf32(gelu_tanh(f3));
            }
            float4 v = make_float4(f0, f1, f2, f3);
            *reinterpret_cast<float4*>(outp + b * 32 + c) = v;
        }
    }
    TC_FENCE_BEFORE();
    __syncthreads();
    if (wid == 0) {
        TC_RELINQ();
        TC_DEALLOC(tmem, 512);
    }
#else
    // ================= tf32 wmma fallback (256 rows = 2 x 128 halves) =========
    using namespace nvcuda;
    constexpr int BM = 128;
    constexpr int BK = 16;
    constexpr int NCH = Kd / BK;
    const float* We = Wsrc + (size_t)e * Kd * Nd;        // expert's [K, N] weights
    // carve dynamic smem
    float* As = reinterpret_cast<float*>(smem);                    // [2][BM][BK+4]
    float* Bs = As + 2 * BM * (BK + 4);                            // [2][BK][BN+8]
    const float** s_arow = reinterpret_cast<const float**>(Bs + 2 * BK * (BN + 8));

    for (int h128 = 0; h128 < 2; h128++) {
        int m0h = m0 + h128 * BM;

        for (int r = tid; r < BM; r += 256) {
            if (WHICH == 1) {
                int tok = g_src[e * CAPACITY + m0h + r];
                s_arow[r] = g_xr + (size_t)tok * Kd;
            } else {
                s_arow[r] = g_h + (size_t)(e * CAPACITY + m0h + r) * Kd;
            }
        }
        __syncthreads();

        auto Aat = [&](int buf, int r, int c) -> float& { return As[(buf * BM + r) * (BK + 4) + c]; };
        auto Bat = [&](int buf, int r, int c) -> float& { return Bs[(buf * BK + r) * (BN + 8) + c]; };

        auto loadA = [&](int buf, int k0) {
#pragma unroll
            for (int it = 0; it < 2; it++) {
                int idx = tid * 2 + it;
                int r = idx >> 2, q = idx & 3;
                float4 v = *reinterpret_cast<const float4*>(s_arow[r] + k0 + q * 4);
                *reinterpret_cast<float4*>(&Aat(buf, r, q * 4)) = v;
            }
        };
        auto loadB = [&](int buf, int k0) {
#pragma unroll
            for (int it = 0; it < 4; it++) {
                int idx = tid + it * 256;
                int r = idx >> 6, c = idx & 63;
                float4 v = *reinterpret_cast<const float4*>(We + (size_t)(k0 + r) * Nd + n0 + c * 4);
                *reinterpret_cast<float4*>(&Bat(buf, r, c * 4)) = v;
            }
        };

        typedef wmma::fragment<wmma::matrix_a, 16, 16, 8, wmma::precision::tf32, wmma::row_major> FragA;
        typedef wmma::fragment<wmma::matrix_b, 16, 16, 8, wmma::precision::tf32, wmma::row_major> FragB;
        typedef wmma::fragment<wmma::accumulator, 16, 16, 8, float> FragC;

        FragC acc[4][4];
#pragma unroll
        for (int i = 0; i < 4; i++)
#pragma unroll
            for (int j = 0; j < 4; j++) wmma::fill_fragment(acc[i][j], 0.f);

        int wm = wid >> 2;     // 0..1  -> 64-row half
        int wn = wid & 3;      // 0..3  -> 64-col quarter

        loadA(0, 0);
        loadB(0, 0);
        __syncthreads();

        for (int ks = 0; ks < NCH; ks++) {
            int cur = ks & 1;
            if (ks + 1 < NCH) { loadA(cur ^ 1, (ks + 1) * BK); loadB(cur ^ 1, (ks + 1) * BK); }
#pragma unroll
            for (int kk = 0; kk < 2; kk++) {
                FragA af[4];
                FragB bf[4];
#pragma unroll
                for (int i = 0; i < 4; i++)
                    wmma::load_matrix_sync(af[i], &Aat(cur, wm * 64 + i * 16, kk * 8), BK + 4);
#pragma unroll
                for (int j = 0; j < 4; j++) {
                    wmma::load_matrix_sync(bf[j], &Bat(cur, kk * 8, wn * 64 + j * 16), BN + 8);
#pragma unroll
                    for (int t = 0; t < bf[j].num_elements; t++)
                        bf[j].x[t] = wmma::__float_to_tf32(bf[j].x[t]);
                }
#pragma unroll
                for (int i = 0; i < 4; i++)
#pragma unroll
                    for (int j = 0; j < 4; j++)
                        wmma::mma_sync(acc[i][j], af[i], bf[j], acc[i][j]);
            }
            __syncthreads();
        }

        float* Cb = ((WHICH == 1) ? g_h : g_y) + (size_t)(e * CAPACITY + m0h) * Nd + n0;
#pragma unroll
        for (int i = 0; i < 4; i++)
#pragma unroll
            for (int j = 0; j < 4; j++) {
                if (WHICH == 1) {
#pragma unroll
                    for (int t = 0; t < acc[i][j].num_elements; t++)
                        acc[i][j].x[t] = to_tf32(gelu_tanh(acc[i][j].x[t]));
                }
                wmma::store_matrix_sync(Cb + (size_t)(wm * 64 + i * 16) * Nd + wn * 64 + j * 16,
                                        acc[i][j], Nd, wmma::mem_row_major);
            }
        __syncthreads();
    }
#endif
}

// ---------------- combine -----------------------------------------------------
__global__ void __launch_bounds__(256) combine_kernel(float* __restrict__ out) {
    int t   = blockIdx.x;
    int tid = threadIdx.x;
    int i0 = g_cidx[2 * t],     i1 = g_cidx[2 * t + 1];
    float w0 = g_cw[2 * t],     w1 = g_cw[2 * t + 1];
    const float4* y0 = reinterpret_cast<const float4*>(g_y + (size_t)i0 * DM);
    const float4* y1 = reinterpret_cast<const float4*>(g_y + (size_t)i1 * DM);
    float4 a = y0[tid], b = y1[tid];
    float4 r;
    r.x = w0 * a.x + w1 * b.x;
    r.y = w0 * a.y + w1 * b.y;
    r.z = w0 * a.z + w1 * b.z;
    r.w = w0 * a.w + w1 * b.w;
    reinterpret_cast<float4*>(out + (size_t)t * DM)[tid] = r;
}

// ---------------- launch ------------------------------------------------------
extern "C" void kernel_launch(void* const* d_in, const int* in_sizes, int n_in,
                              void* d_out, int out_size) {
    const float* x  = (const float*)d_in[0];   // [T, D]
    const float* Wg = (const float*)d_in[1];   // [D, E]
    const float* W1 = (const float*)d_in[2];   // [E, D, H]
    const float* W2 = (const float*)d_in[3];   // [E, H, D]
    float* out = (float*)d_out;                // [T, D]

    cudaFuncSetAttribute(moe_gemm_tc<1>, cudaFuncAttributeMaxDynamicSharedMemorySize, SMEM_SZ);
    cudaFuncSetAttribute(moe_gemm_tc<2>, cudaFuncAttributeMaxDynamicSharedMemorySize, SMEM_SZ);

    router_kernel<<<NT / 8, 256>>>(x, Wg);
    convert_x_kernel<<<(NT * DM) / 1024, 256>>>(x);
    {
        float* w1t; cudaGetSymbolAddress((void**)&w1t, g_w1t);
        transpose_w_kernel<<<dim3(DFF / 32, DM / 32, NE), 256>>>(W1, w1t, DM, DFF);
    }
    {
        float* w2t; cudaGetSymbolAddress((void**)&w2t, g_w2t);
        transpose_w_kernel<<<dim3(DM / 32, DFF / 32, NE), 256>>>(W2, w2t, DFF, DM);
    }
    scan_kernel<<<1, 256>>>();
    moe_gemm_tc<1><<<dim3(CAPACITY / BMP, DFF / BN, NE), 256, SMEM_SZ>>>(W1);
    moe_gemm_tc<2><<<dim3(CAPACITY / BMP, DM  / BN, NE), 256, SMEM_SZ>>>(W2);
    combine_kernel<<<NT, 256>>>(out);
}

// round 8
// speedup vs baseline: 6.6032x; 1.2289x over previous
#include <cuda_runtime.h>
#include <mma.h>
#include <math.h>
#include <stdint.h>

#define NE 7
#define TOPK 2
#define CAPACITY 3072
#define DM 1024
#define DFF 4096
#define NT 8192
#define TK (NT*TOPK)

#define MT1 (CAPACITY/256)    // 12 m-tiles
#define NT1 (DFF/256)         // 16 n-tiles (GEMM1)
#define NT2 (DM/256)          // 4  n-tiles (GEMM2)
#define NCH1 (DM/32)          // 32 k-chunks (GEMM1)
#define NCH2 (DFF/32)         // 128 k-chunks (GEMM2)
#define CHUNK_BYTES 32768     // 256 rows x 128B

#if defined(__CUDA_ARCH__) && defined(__CUDA_ARCH_FEAT_SM103_ALL)
#define HAS_TC 1
#else
#define HAS_TC 0
#endif

// ---------------- scratch (device globals; no allocations allowed) ----------
__device__ int   g_te[TK];
__device__ float g_tw[TK];
__device__ int   g_src[NE*CAPACITY];
__device__ int   g_cnt[NE];
__device__ int   g_cidx[TK];
__device__ float g_cw[TK];
__device__ float g_abuf[(size_t)NE*MT1*NCH1*8192];   // x gathered, chunked+swizzled (88MB)
__device__ float g_w1t[(size_t)NE*(size_t)DFF*DM];   // W1^T chunked [e][nt][k][32KB]
__device__ float g_w2t[(size_t)NE*(size_t)DM*DFF];   // W2^T chunked [e][nt][k][32KB]
__device__ float g_h[(size_t)NE*CAPACITY*DFF];       // h chunked [e][mt][k2][32KB] (TC) / row-major (fallback)
__device__ float g_y[(size_t)NE*CAPACITY*DM];        // row-major

// ---------------- common helpers ---------------------------------------------
__device__ __forceinline__ float to_tf32(float f) {
    float r; asm("cvt.rna.tf32.f32 %0, %1;" : "=f"(r) : "f"(f)); return r;
}
__device__ __forceinline__ float gelu_tanh(float v) {
    float c = 0.7978845608028654f * (v + 0.044715f * v * v * v);
    return 0.5f * v * (1.f + tanhf(c));
}
__device__ __forceinline__ uint32_t smem_u32(const void* p) {
    uint32_t a;
    asm("{ .reg .u64 t; cvta.to.shared.u64 t, %1; cvt.u32.u64 %0, t; }" : "=r"(a) : "l"(p));
    return a;
}
__device__ __forceinline__ uint32_t swz(uint32_t b) { return b ^ ((b >> 3) & 0x70); }

#if HAS_TC
// ---------------- tcgen05 / TMA-bulk PTX helpers ------------------------------
__device__ __forceinline__ void bulk_g2s(uint32_t dst, const void* src, uint32_t bytes,
                                         uint32_t mbar) {
    asm volatile(
        "cp.async.bulk.shared::cluster.global.mbarrier::complete_tx::bytes [%0], [%1], %2, [%3];"
        :: "r"(dst), "l"(src), "r"(bytes), "r"(mbar) : "memory");
}
__device__ __forceinline__ void mbar_init(uint32_t a, uint32_t cnt) {
    asm volatile("mbarrier.init.shared.b64 [%0], %1;" :: "r"(a), "r"(cnt) : "memory");
}
__device__ __forceinline__ void mbar_expect_tx(uint32_t a, uint32_t bytes) {
    asm volatile("mbarrier.arrive.expect_tx.shared.b64 _, [%0], %1;" :: "r"(a), "r"(bytes) : "memory");
}
__device__ __forceinline__ void mbar_wait(uint32_t a, uint32_t parity) {
    asm volatile(
        "{\n\t.reg .pred P;\n\t"
        "WAITLOOP_%=:\n\t"
        "mbarrier.try_wait.parity.acquire.cta.shared::cta.b64 P, [%0], %1, 0x989680;\n\t"
        "@P bra.uni WDONE_%=;\n\t"
        "bra.uni WAITLOOP_%=;\n\t"
        "WDONE_%=:\n\t}"
        :: "r"(a), "r"(parity) : "memory");
}

#define TC_ALLOC(smaddr, n)  asm volatile("tcgen05.alloc.cta_group::1.sync.aligned.shared::cta.b32 [%0], %1;" :: "r"(smaddr), "r"((uint32_t)(n)) : "memory")
#define TC_DEALLOC(tm, n)    asm volatile("tcgen05.dealloc.cta_group::1.sync.aligned.b32 %0, %1;" :: "r"(tm), "r"((uint32_t)(n)))
#define TC_RELINQ()          asm volatile("tcgen05.relinquish_alloc_permit.cta_group::1.sync.aligned;")
#define TC_COMMIT(mb)        asm volatile("tcgen05.commit.cta_group::1.mbarrier::arrive::one.shared::cluster.b64 [%0];" :: "r"(mb) : "memory")
#define TC_WAIT_LD()         asm volatile("tcgen05.wait::ld.sync.aligned;" ::: "memory")
#define TC_FENCE_BEFORE()    asm volatile("tcgen05.fence::before_thread_sync;" ::: "memory")
#define TC_FENCE_AFTER()     asm volatile("tcgen05.fence::after_thread_sync;" ::: "memory")
#define FENCE_ASYNC_SHARED() asm volatile("fence.proxy.async.shared::cta;" ::: "memory")

__device__ __forceinline__ void mma_tf32_ss(uint32_t d, uint64_t ad, uint64_t bd,
                                            uint32_t idesc, uint32_t en) {
    asm volatile(
        "{\n\t.reg .pred p;\n\t"
        "setp.ne.u32 p, %4, 0;\n\t"
        "tcgen05.mma.cta_group::1.kind::tf32 [%0], %1, %2, %3, p;\n\t}"
        :: "r"(d), "l"(ad), "l"(bd), "r"(idesc), "r"(en) : "memory");
}
// K-major SW128 smem descriptor (LBO=1, SBO=64, version=1, layout=SW128)
__device__ __forceinline__ uint64_t mkdesc(uint32_t addr) {
    return (uint64_t)((addr >> 4) & 0x3FFF)
         | (1ull << 16) | (64ull << 32) | (1ull << 46) | (2ull << 61);
}
#define TC_LD_X32(r, tm) \
    asm volatile( \
        "tcgen05.ld.sync.aligned.32x32b.x32.b32 " \
        "{%0, %1, %2, %3, %4, %5, %6, %7, " \
        " %8, %9, %10, %11, %12, %13, %14, %15, " \
        " %16, %17, %18, %19, %20, %21, %22, %23, " \
        " %24, %25, %26, %27, %28, %29, %30, %31}, [%32];" \
        : "=r"((r)[0]),  "=r"((r)[1]),  "=r"((r)[2]),  "=r"((r)[3]), \
          "=r"((r)[4]),  "=r"((r)[5]),  "=r"((r)[6]),  "=r"((r)[7]), \
          "=r"((r)[8]),  "=r"((r)[9]),  "=r"((r)[10]), "=r"((r)[11]), \
          "=r"((r)[12]), "=r"((r)[13]), "=r"((r)[14]), "=r"((r)[15]), \
          "=r"((r)[16]), "=r"((r)[17]), "=r"((r)[18]), "=r"((r)[19]), \
          "=r"((r)[20]), "=r"((r)[21]), "=r"((r)[22]), "=r"((r)[23]), \
          "=r"((r)[24]), "=r"((r)[25]), "=r"((r)[26]), "=r"((r)[27]), \
          "=r"((r)[28]), "=r"((r)[29]), "=r"((r)[30]), "=r"((r)[31]) \
        : "r"(tm))
#endif  // HAS_TC

// ---------------- router ------------------------------------------------------
__global__ void __launch_bounds__(256) router_kernel(const float* __restrict__ x,
                                                     const float* __restrict__ Wg) {
    int wid  = threadIdx.x >> 5;
    int lane = threadIdx.x & 31;
    int t = blockIdx.x * 8 + wid;
    if (t >= NT) return;

    float acc[NE];
#pragma unroll
    for (int e = 0; e < NE; e++) acc[e] = 0.f;

    const float4* xr = reinterpret_cast<const float4*>(x + (size_t)t * DM);
#pragma unroll 4
    for (int i = lane; i < DM / 4; i += 32) {
        float4 v = xr[i];
        int d = i * 4;
#pragma unroll
        for (int e = 0; e < NE; e++) {
            acc[e] += v.x * Wg[(d + 0) * NE + e];
            acc[e] += v.y * Wg[(d + 1) * NE + e];
            acc[e] += v.z * Wg[(d + 2) * NE + e];
            acc[e] += v.w * Wg[(d + 3) * NE + e];
        }
    }
#pragma unroll
    for (int e = 0; e < NE; e++)
#pragma unroll
        for (int off = 16; off > 0; off >>= 1)
            acc[e] += __shfl_xor_sync(0xffffffffu, acc[e], off);

    if (lane == 0) {
        float l0 = -1e30f; int e0 = 0;
#pragma unroll
        for (int e = 0; e < NE; e++) if (acc[e] > l0) { l0 = acc[e]; e0 = e; }
        float l1 = -1e30f; int e1 = 0;
#pragma unroll
        for (int e = 0; e < NE; e++) if (e != e0 && acc[e] > l1) { l1 = acc[e]; e1 = e; }
        float w0 = 1.f / (1.f + __expf(l1 - l0));
        g_te[2 * t]     = e0;  g_te[2 * t + 1] = e1;
        g_tw[2 * t]     = w0;  g_tw[2 * t + 1] = 1.f - w0;
    }
}

// ---------------- ordered capacity scan --------------------------------------
__global__ void __launch_bounds__(256) scan_kernel() {
    __shared__ int s_run[NE];
    __shared__ int s_wtot[8][NE];
    int tid  = threadIdx.x;
    int wid  = tid >> 5;
    int lane = tid & 31;
    if (tid < NE) s_run[tid] = 0;
    __syncthreads();

    for (int base = 0; base < TK; base += 256) {
        int i = base + tid;
        int e = g_te[i];
        int rank = 0;
#pragma unroll
        for (int ee = 0; ee < NE; ee++) {
            unsigned m = __ballot_sync(0xffffffffu, e == ee);
            if (e == ee) rank = __popc(m & ((1u << lane) - 1u));
            if (lane == 0) s_wtot[wid][ee] = __popc(m);
        }
        __syncthreads();
        int off = s_run[e];
        for (int w = 0; w < wid; w++) off += s_wtot[w][e];
        int pos = off + rank;
        if (pos < CAPACITY) {
            g_src[e * CAPACITY + pos] = i >> 1;
            g_cidx[i] = e * CAPACITY + pos;
            g_cw[i]   = g_tw[i];
        } else {
            g_cidx[i] = 0;
            g_cw[i]   = 0.f;
        }
        __syncthreads();
        if (tid < NE) {
            int tot = 0;
#pragma unroll
            for (int w = 0; w < 8; w++) tot += s_wtot[w][tid];
            s_run[tid] += tot;
        }
        __syncthreads();
    }
    if (tid < NE) g_cnt[tid] = min(s_run[tid], CAPACITY);
    __syncthreads();
    for (int idx = tid; idx < NE * CAPACITY; idx += 256) {
        int e = idx / CAPACITY, c = idx % CAPACITY;
        if (c >= min(s_run[e], CAPACITY)) g_src[idx] = 0;
    }
}

// ---------------- dispatch: gather x rows into chunked swizzled A ------------
__global__ void __launch_bounds__(256) dispatch_kernel(const float* __restrict__ x) {
    int slot = blockIdx.x;                 // 0 .. NE*CAPACITY-1
    int e  = slot / CAPACITY;
    int sl = slot % CAPACITY;
    int mt = sl >> 8, row = sl & 255;
    int tok = g_src[slot];
    int t = threadIdx.x;
    int k = t >> 3, seg = t & 7;           // chunk k (0..31), 16B segment (0..7)

    float4 v = *reinterpret_cast<const float4*>(x + (size_t)tok * DM + k * 32 + seg * 4);
    v.x = to_tf32(v.x); v.y = to_tf32(v.y); v.z = to_tf32(v.z); v.w = to_tf32(v.w);

    size_t cb = (((size_t)e * MT1 + mt) * NCH1 + k) * CHUNK_BYTES;
    uint32_t off = swz((uint32_t)(row * 128 + seg * 16));
    *reinterpret_cast<float4*>(reinterpret_cast<char*>(g_abuf) + cb + off) = v;
}

// ---------------- repack W: transpose + round + chunk + swizzle ---------------
// W [e][KD][ND] -> Wc chunks [e][nt=ND/256][k=KD/32][256x128B SW128]
__global__ void __launch_bounds__(256) repack_w_kernel(const float* __restrict__ W,
                                                       float* __restrict__ Wc,
                                                       int KD, int ND) {
    __shared__ float t[32][33];
    int e = blockIdx.z;
    int n0 = blockIdx.x * 32, k0 = blockIdx.y * 32;
    const float* src = W + (size_t)e * KD * ND;
    int tx = threadIdx.x & 31, ty = threadIdx.x >> 5;   // 32 x 8
#pragma unroll
    for (int r = 0; r < 32; r += 8)
        t[ty + r][tx] = src[(size_t)(k0 + ty + r) * ND + n0 + tx];
    __syncthreads();
    int nchunks = KD >> 5;
    int chunk = k0 >> 5;                    // k0 multiple of 32
#pragma unroll
    for (int r = 0; r < 32; r += 8) {
        int n = n0 + ty + r;
        int k = k0 + tx;
        float val = to_tf32(t[tx][ty + r]);
        size_t cb = (((size_t)e * (ND >> 8) + (n >> 8)) * nchunks + chunk) * CHUNK_BYTES;
        uint32_t off = swz((uint32_t)((n & 255) * 128 + (k & 31) * 4));
        *reinterpret_cast<float*>(reinterpret_cast<char*>(Wc) + cb + off) = val;
    }
}

// ---------------- grouped GEMM: bulk-TMA warp-specialized tcgen05 -------------
#define BMP 256
#define BN 256
#define STAGES 3
#define STAGE_BYTES (2*CHUNK_BYTES)        // A 32KB + B 32KB
#define SMEM_SZ (2048 + STAGES*STAGE_BYTES)

// idesc: c=F32(1<<4), a=TF32(2<<7), b=TF32(2<<10), N=256 (32<<17), M=128 (8<<24)
#define IDESC ((1u<<4) | (2u<<7) | (2u<<10) | ((BN/8)<<17) | ((128/16)<<24))

template <int WHICH>
__global__ void __launch_bounds__(256, 1) moe_gemm_tc(const float* __restrict__ Wsrc,
                                                      const float* __restrict__ Xsrc) {
    constexpr int Kd  = (WHICH == 1) ? DM : DFF;
    constexpr int Nd  = (WHICH == 1) ? DFF : DM;
    constexpr int NCH = Kd / 32;

    int e  = blockIdx.z;
    int mt = blockIdx.x;
    int nt = blockIdx.y;
    int m0 = mt * BMP;
    int n0 = nt * BN;
    if (m0 >= g_cnt[e]) return;

    extern __shared__ char smem[];
    int tid = threadIdx.x, wid = tid >> 5, lane = tid & 31;

#if HAS_TC
    (void)Wsrc; (void)Xsrc;
    uint32_t sb = smem_u32(smem);
    uint32_t tmp_addr = sb;                       // tcgen05.alloc result
    uint32_t mb_full  = sb + 16;                  // 3 x 8B
    uint32_t mb_empty = sb + 40;                  // 3 x 8B
    uint32_t mb_done  = sb + 64;
    uint32_t stage0 = (sb + 128 + 1023) & ~1023u;

    const char* abase;
    if (WHICH == 1) abase = reinterpret_cast<const char*>(g_abuf)
                          + (((size_t)e * MT1 + mt) * NCH1) * CHUNK_BYTES;
    else            abase = reinterpret_cast<const char*>(g_h)
                          + (((size_t)e * MT1 + mt) * NCH2) * CHUNK_BYTES;
    const char* bbase;
    if (WHICH == 1) bbase = reinterpret_cast<const char*>(g_w1t)
                          + (((size_t)e * NT1 + nt) * NCH1) * CHUNK_BYTES;
    else            bbase = reinterpret_cast<const char*>(g_w2t)
                          + (((size_t)e * NT2 + nt) * NCH2) * CHUNK_BYTES;

    if (tid == 0) {
        for (int j = 0; j < 3; j++) { mbar_init(mb_full + j * 8, 1); mbar_init(mb_empty + j * 8, 1); }
        mbar_init(mb_done, 1);
        FENCE_ASYNC_SHARED();
    }
    if (wid == 0) TC_ALLOC(tmp_addr, 512);
    __syncthreads();
    uint32_t tmem;
    asm volatile("ld.shared.b32 %0, [%1];" : "=r"(tmem) : "r"(tmp_addr));

    if (tid == 0) {
        // ---- producer: one bulk copy per operand per chunk ----
        for (int i = 0; i < NCH; i++) {
            int s = i % 3, ep = i / 3;
            if (ep >= 1) mbar_wait(mb_empty + s * 8, (ep - 1) & 1);
            uint32_t st = stage0 + s * STAGE_BYTES;
            mbar_expect_tx(mb_full + s * 8, STAGE_BYTES);
            bulk_g2s(st,               abase + (size_t)i * CHUNK_BYTES, CHUNK_BYTES, mb_full + s * 8);
            bulk_g2s(st + CHUNK_BYTES, bbase + (size_t)i * CHUNK_BYTES, CHUNK_BYTES, mb_full + s * 8);
        }
    } else if (tid == 32) {
        // ---- MMA issue ----
        for (int i = 0; i < NCH; i++) {
            int s = i % 3, ep = i / 3;
            mbar_wait(mb_full + s * 8, ep & 1);
            uint64_t ad0 = mkdesc(stage0 + s * STAGE_BYTES);
            uint64_t ad1 = ad0 + 1024;                       // +128 rows
            uint64_t bd  = mkdesc(stage0 + s * STAGE_BYTES + CHUNK_BYTES);
#pragma unroll
            for (int st = 0; st < 4; st++) {
                uint32_t en = (i > 0) || (st > 0);
                mma_tf32_ss(tmem,       ad0 + st * 2, bd + st * 2, IDESC, en);
                mma_tf32_ss(tmem + 256, ad1 + st * 2, bd + st * 2, IDESC, en);
            }
            TC_COMMIT(mb_empty + s * 8);
        }
        TC_COMMIT(mb_done);
    }

    // ---- all threads: wait for final MMA, then epilogue ----
    mbar_wait(mb_done, 0);
    TC_FENCE_AFTER();

    int part = wid & 3, tb = wid >> 2;
    int srow = tb * 128 + part * 32 + lane;             // row within 256-tile
    uint32_t dbase = tmem + tb * 256;
    if (WHICH == 1) {
        // write h in GEMM2's chunked layout
        char* hb = reinterpret_cast<char*>(g_h)
                 + (((size_t)e * MT1 + mt) * NCH2 + (n0 >> 5)) * CHUNK_BYTES;
#pragma unroll
        for (int b = 0; b < 8; b++) {
            uint32_t u[32];
            TC_LD_X32(u, dbase + b * 32);
            TC_WAIT_LD();
            char* cb = hb + (size_t)b * CHUNK_BYTES;
#pragma unroll
            for (int c = 0; c < 32; c += 4) {
                float4 v = make_float4(
                    to_tf32(gelu_tanh(__uint_as_float(u[c + 0]))),
                    to_tf32(gelu_tanh(__uint_as_float(u[c + 1]))),
                    to_tf32(gelu_tanh(__uint_as_float(u[c + 2]))),
                    to_tf32(gelu_tanh(__uint_as_float(u[c + 3]))));
                uint32_t off = swz((uint32_t)(srow * 128 + (c >> 2) * 16));
                *reinterpret_cast<float4*>(cb + off) = v;
            }
        }
    } else {
        float* outp = g_y + ((size_t)(e * CAPACITY + m0 + srow)) * Nd + n0;
#pragma unroll
        for (int b = 0; b < 8; b++) {
            uint32_t u[32];
            TC_LD_X32(u, dbase + b * 32);
            TC_WAIT_LD();
#pragma unroll
            for (int c = 0; c < 32; c += 4) {
                float4 v = make_float4(__uint_as_float(u[c + 0]), __uint_as_float(u[c + 1]),
                                       __uint_as_float(u[c + 2]), __uint_as_float(u[c + 3]));
                *reinterpret_cast<float4*>(outp + b * 32 + c) = v;
            }
        }
    }
    TC_FENCE_BEFORE();
    __syncthreads();
    if (wid == 0) {
        TC_RELINQ();
        TC_DEALLOC(tmem, 512);
    }
#else
    // ================= tf32 wmma fallback (row-major h; internally consistent) =====
    using namespace nvcuda;
    constexpr int BM = 128;
    constexpr int BK = 16;
    constexpr int NKS = Kd / BK;
    const float* We = Wsrc + (size_t)e * Kd * Nd;
    float* As = reinterpret_cast<float*>(smem);
    float* Bs = As + 2 * BM * (BK + 4);
    const float** s_arow = reinterpret_cast<const float**>(Bs + 2 * BK * (BN + 8));

    for (int h128 = 0; h128 < 2; h128++) {
        int m0h = m0 + h128 * BM;
        for (int r = tid; r < BM; r += 256) {
            if (WHICH == 1) s_arow[r] = Xsrc + (size_t)g_src[e * CAPACITY + m0h + r] * Kd;
            else            s_arow[r] = g_h + (size_t)(e * CAPACITY + m0h + r) * Kd;
        }
        __syncthreads();
        auto Aat = [&](int buf, int r, int c) -> float& { return As[(buf * BM + r) * (BK + 4) + c]; };
        auto Bat = [&](int buf, int r, int c) -> float& { return Bs[(buf * BK + r) * (BN + 8) + c]; };
        auto loadA = [&](int buf, int k0) {
#pragma unroll
            for (int it = 0; it < 2; it++) {
                int idx = tid * 2 + it;
                int r = idx >> 2, q = idx & 3;
                float4 v = *reinterpret_cast<const float4*>(s_arow[r] + k0 + q * 4);
                *reinterpret_cast<float4*>(&Aat(buf, r, q * 4)) = v;
            }
        };
        auto loadB = [&](int buf, int k0) {
#pragma unroll
            for (int it = 0; it < 4; it++) {
                int idx = tid + it * 256;
                int r = idx >> 6, c = idx & 63;
                float4 v = *reinterpret_cast<const float4*>(We + (size_t)(k0 + r) * Nd + n0 + c * 4);
                *reinterpret_cast<float4*>(&Bat(buf, r, c * 4)) = v;
            }
        };
        typedef wmma::fragment<wmma::matrix_a, 16, 16, 8, wmma::precision::tf32, wmma::row_major> FragA;
        typedef wmma::fragment<wmma::matrix_b, 16, 16, 8, wmma::precision::tf32, wmma::row_major> FragB;
        typedef wmma::fragment<wmma::accumulator, 16, 16, 8, float> FragC;
        FragC acc[4][4];
#pragma unroll
        for (int i = 0; i < 4; i++)
#pragma unroll
            for (int j = 0; j < 4; j++) wmma::fill_fragment(acc[i][j], 0.f);
        int wm = wid >> 2, wn = wid & 3;
        loadA(0, 0); loadB(0, 0);
        __syncthreads();
        for (int ks = 0; ks < NKS; ks++) {
            int cur = ks & 1;
            if (ks + 1 < NKS) { loadA(cur ^ 1, (ks + 1) * BK); loadB(cur ^ 1, (ks + 1) * BK); }
#pragma unroll
            for (int kk = 0; kk < 2; kk++) {
                FragA af[4]; FragB bf[4];
#pragma unroll
                for (int i = 0; i < 4; i++) {
                    wmma::load_matrix_sync(af[i], &Aat(cur, wm * 64 + i * 16, kk * 8), BK + 4);
#pragma unroll
                    for (int t = 0; t < af[i].num_elements; t++)
                        af[i].x[t] = wmma::__float_to_tf32(af[i].x[t]);
                }
#pragma unroll
                for (int j = 0; j < 4; j++) {
                    wmma::load_matrix_sync(bf[j], &Bat(cur, kk * 8, wn * 64 + j * 16), BN + 8);
#pragma unroll
                    for (int t = 0; t < bf[j].num_elements; t++)
                        bf[j].x[t] = wmma::__float_to_tf32(bf[j].x[t]);
                }
#pragma unroll
                for (int i = 0; i < 4; i++)
#pragma unroll
                    for (int j = 0; j < 4; j++)
                        wmma::mma_sync(acc[i][j], af[i], bf[j], acc[i][j]);
            }
            __syncthreads();
        }
        float* Cb = ((WHICH == 1) ? g_h : g_y) + (size_t)(e * CAPACITY + m0h) * Nd + n0;
#pragma unroll
        for (int i = 0; i < 4; i++)
#pragma unroll
            for (int j = 0; j < 4; j++) {
                if (WHICH == 1) {
#pragma unroll
                    for (int t = 0; t < acc[i][j].num_elements; t++)
                        acc[i][j].x[t] = to_tf32(gelu_tanh(acc[i][j].x[t]));
                }
                wmma::store_matrix_sync(Cb + (size_t)(wm * 64 + i * 16) * Nd + wn * 64 + j * 16,
                                        acc[i][j], Nd, wmma::mem_row_major);
            }
        __syncthreads();
    }
#endif
}

// ---------------- combine -----------------------------------------------------
__global__ void __launch_bounds__(256) combine_kernel(float* __restrict__ out) {
    int t   = blockIdx.x;
    int tid = threadIdx.x;
    int i0 = g_cidx[2 * t],     i1 = g_cidx[2 * t + 1];
    float w0 = g_cw[2 * t],     w1 = g_cw[2 * t + 1];
    const float4* y0 = reinterpret_cast<const float4*>(g_y + (size_t)i0 * DM);
    const float4* y1 = reinterpret_cast<const float4*>(g_y + (size_t)i1 * DM);
    float4 a = y0[tid], b = y1[tid];
    float4 r;
    r.x = w0 * a.x + w1 * b.x;
    r.y = w0 * a.y + w1 * b.y;
    r.z = w0 * a.z + w1 * b.z;
    r.w = w0 * a.w + w1 * b.w;
    reinterpret_cast<float4*>(out + (size_t)t * DM)[tid] = r;
}

// ---------------- launch ------------------------------------------------------
extern "C" void kernel_launch(void* const* d_in, const int* in_sizes, int n_in,
                              void* d_out, int out_size) {
    const float* x  = (const float*)d_in[0];   // [T, D]
    const float* Wg = (const float*)d_in[1];   // [D, E]
    const float* W1 = (const float*)d_in[2];   // [E, D, H]
    const float* W2 = (const float*)d_in[3];   // [E, H, D]
    float* out = (float*)d_out;                // [T, D]

    cudaFuncSetAttribute(moe_gemm_tc<1>, cudaFuncAttributeMaxDynamicSharedMemorySize, SMEM_SZ);
    cudaFuncSetAttribute(moe_gemm_tc<2>, cudaFuncAttributeMaxDynamicSharedMemorySize, SMEM_SZ);

    router_kernel<<<NT / 8, 256>>>(x, Wg);
    {
        float* w1t; cudaGetSymbolAddress((void**)&w1t, g_w1t);
        repack_w_kernel<<<dim3(DFF / 32, DM / 32, NE), 256>>>(W1, w1t, DM, DFF);
    }
    {
        float* w2t; cudaGetSymbolAddress((void**)&w2t, g_w2t);
        repack_w_kernel<<<dim3(DM / 32, DFF / 32, NE), 256>>>(W2, w2t, DFF, DM);
    }
    scan_kernel<<<1, 256>>>();
    dispatch_kernel<<<NE * CAPACITY, 256>>>(x);
    moe_gemm_tc<1><<<dim3(MT1, NT1, NE), 256, SMEM_SZ>>>(W1, x);
    moe_gemm_tc<2><<<dim3(MT1, NT2, NE), 256, SMEM_SZ>>>(W2, x);
    combine_kernel<<<NT, 256>>>(out);
}

// round 9
// speedup vs baseline: 7.2282x; 1.0947x over previous
#include <cuda_runtime.h>
#include <mma.h>
#include <math.h>
#include <stdint.h>

#define NE 7
#define TOPK 2
#define CAPACITY 3072
#define DM 1024
#define DFF 4096
#define NT 8192
#define TK (NT*TOPK)
#define NSEG 64                // TK / 256

#define MT1 (CAPACITY/256)    // 12 m-tiles
#define NT1 (DFF/256)         // 16 n-tiles (GEMM1)
#define NT2 (DM/256)          // 4  n-tiles (GEMM2)
#define NCH1 (DM/32)          // 32 k-chunks (GEMM1)
#define NCH2 (DFF/32)         // 128 k-chunks (GEMM2)
#define CHUNK_BYTES 32768     // 256 rows x 128B

#if defined(__CUDA_ARCH__) && defined(__CUDA_ARCH_FEAT_SM103_ALL)
#define HAS_TC 1
#else
#define HAS_TC 0
#endif

// ---------------- scratch (device globals; no allocations allowed) ----------
__device__ int   g_te[TK];
__device__ float g_tw[TK];
__device__ int   g_src[NE*CAPACITY];
__device__ int   g_cnt[NE];              // capped per-expert counts
__device__ int   g_run[NE];              // raw (uncapped) totals
__device__ int   g_blkcnt[NSEG*NE];      // per-segment expert histograms
__device__ int   g_segoff[NSEG*NE];      // exclusive prefix per expert
__device__ int   g_cidx[TK];
__device__ float g_cw[TK];
__device__ float g_abuf[(size_t)NE*MT1*NCH1*8192];   // x gathered, chunked+swizzled
__device__ float g_w1t[(size_t)NE*(size_t)DFF*DM];   // W1^T chunked [e][nt][k][32KB]
__device__ float g_w2t[(size_t)NE*(size_t)DM*DFF];   // W2^T chunked [e][nt][k][32KB]
__device__ float g_h[(size_t)NE*CAPACITY*DFF];       // h chunked (TC) / row-major (fallback)
__device__ float g_y[(size_t)NE*CAPACITY*DM];        // row-major

// ---------------- common helpers ---------------------------------------------
__device__ __forceinline__ float to_tf32(float f) {
    float r; asm("cvt.rna.tf32.f32 %0, %1;" : "=f"(r) : "f"(f)); return r;
}
__device__ __forceinline__ float gelu_tanh(float v) {
    float c = 0.7978845608028654f * (v + 0.044715f * v * v * v);
    return 0.5f * v * (1.f + tanhf(c));
}
__device__ __forceinline__ uint32_t smem_u32(const void* p) {
    uint32_t a;
    asm("{ .reg .u64 t; cvta.to.shared.u64 t, %1; cvt.u32.u64 %0, t; }" : "=r"(a) : "l"(p));
    return a;
}
__device__ __forceinline__ uint32_t swz(uint32_t b) { return b ^ ((b >> 3) & 0x70); }

#if HAS_TC
// ---------------- tcgen05 / TMA-bulk PTX helpers ------------------------------
__device__ __forceinline__ void bulk_g2s(uint32_t dst, const void* src, uint32_t bytes,
                                         uint32_t mbar) {
    asm volatile(
        "cp.async.bulk.shared::cluster.global.mbarrier::complete_tx::bytes [%0], [%1], %2, [%3];"
        :: "r"(dst), "l"(src), "r"(bytes), "r"(mbar) : "memory");
}
__device__ __forceinline__ void mbar_init(uint32_t a, uint32_t cnt) {
    asm volatile("mbarrier.init.shared.b64 [%0], %1;" :: "r"(a), "r"(cnt) : "memory");
}
__device__ __forceinline__ void mbar_expect_tx(uint32_t a, uint32_t bytes) {
    asm volatile("mbarrier.arrive.expect_tx.shared.b64 _, [%0], %1;" :: "r"(a), "r"(bytes) : "memory");
}
__device__ __forceinline__ void mbar_wait(uint32_t a, uint32_t parity) {
    asm volatile(
        "{\n\t.reg .pred P;\n\t"
        "WAITLOOP_%=:\n\t"
        "mbarrier.try_wait.parity.acquire.cta.shared::cta.b64 P, [%0], %1, 0x989680;\n\t"
        "@P bra.uni WDONE_%=;\n\t"
        "bra.uni WAITLOOP_%=;\n\t"
        "WDONE_%=:\n\t}"
        :: "r"(a), "r"(parity) : "memory");
}

#define TC_ALLOC(smaddr, n)  asm volatile("tcgen05.alloc.cta_group::1.sync.aligned.shared::cta.b32 [%0], %1;" :: "r"(smaddr), "r"((uint32_t)(n)) : "memory")
#define TC_DEALLOC(tm, n)    asm volatile("tcgen05.dealloc.cta_group::1.sync.aligned.b32 %0, %1;" :: "r"(tm), "r"((uint32_t)(n)))
#define TC_RELINQ()          asm volatile("tcgen05.relinquish_alloc_permit.cta_group::1.sync.aligned;")
#define TC_COMMIT(mb)        asm volatile("tcgen05.commit.cta_group::1.mbarrier::arrive::one.shared::cluster.b64 [%0];" :: "r"(mb) : "memory")
#define TC_WAIT_LD()         asm volatile("tcgen05.wait::ld.sync.aligned;" ::: "memory")
#define TC_FENCE_BEFORE()    asm volatile("tcgen05.fence::before_thread_sync;" ::: "memory")
#define TC_FENCE_AFTER()     asm volatile("tcgen05.fence::after_thread_sync;" ::: "memory")
#define FENCE_ASYNC_SHARED() asm volatile("fence.proxy.async.shared::cta;" ::: "memory")

__device__ __forceinline__ void mma_tf32_ss(uint32_t d, uint64_t ad, uint64_t bd,
                                            uint32_t idesc, uint32_t en) {
    asm volatile(
        "{\n\t.reg .pred p;\n\t"
        "setp.ne.u32 p, %4, 0;\n\t"
        "tcgen05.mma.cta_group::1.kind::tf32 [%0], %1, %2, %3, p;\n\t}"
        :: "r"(d), "l"(ad), "l"(bd), "r"(idesc), "r"(en) : "memory");
}
// K-major SW128 smem descriptor (LBO=1, SBO=64, version=1, layout=SW128)
__device__ __forceinline__ uint64_t mkdesc(uint32_t addr) {
    return (uint64_t)((addr >> 4) & 0x3FFF)
         | (1ull << 16) | (64ull << 32) | (1ull << 46) | (2ull << 61);
}
#define TC_LD_X32(r, tm) \
    asm volatile( \
        "tcgen05.ld.sync.aligned.32x32b.x32.b32 " \
        "{%0, %1, %2, %3, %4, %5, %6, %7, " \
        " %8, %9, %10, %11, %12, %13, %14, %15, " \
        " %16, %17, %18, %19, %20, %21, %22, %23, " \
        " %24, %25, %26, %27, %28, %29, %30, %31}, [%32];" \
        : "=r"((r)[0]),  "=r"((r)[1]),  "=r"((r)[2]),  "=r"((r)[3]), \
          "=r"((r)[4]),  "=r"((r)[5]),  "=r"((r)[6]),  "=r"((r)[7]), \
          "=r"((r)[8]),  "=r"((r)[9]),  "=r"((r)[10]), "=r"((r)[11]), \
          "=r"((r)[12]), "=r"((r)[13]), "=r"((r)[14]), "=r"((r)[15]), \
          "=r"((r)[16]), "=r"((r)[17]), "=r"((r)[18]), "=r"((r)[19]), \
          "=r"((r)[20]), "=r"((r)[21]), "=r"((r)[22]), "=r"((r)[23]), \
          "=r"((r)[24]), "=r"((r)[25]), "=r"((r)[26]), "=r"((r)[27]), \
          "=r"((r)[28]), "=r"((r)[29]), "=r"((r)[30]), "=r"((r)[31]) \
        : "r"(tm))
#endif  // HAS_TC

// ---------------- router ------------------------------------------------------
__global__ void __launch_bounds__(256) router_kernel(const float* __restrict__ x,
                                                     const float* __restrict__ Wg) {
    int wid  = threadIdx.x >> 5;
    int lane = threadIdx.x & 31;
    int t = blockIdx.x * 8 + wid;
    if (t >= NT) return;

    float acc[NE];
#pragma unroll
    for (int e = 0; e < NE; e++) acc[e] = 0.f;

    const float4* xr = reinterpret_cast<const float4*>(x + (size_t)t * DM);
#pragma unroll 4
    for (int i = lane; i < DM / 4; i += 32) {
        float4 v = xr[i];
        int d = i * 4;
#pragma unroll
        for (int e = 0; e < NE; e++) {
            acc[e] += v.x * Wg[(d + 0) * NE + e];
            acc[e] += v.y * Wg[(d + 1) * NE + e];
            acc[e] += v.z * Wg[(d + 2) * NE + e];
            acc[e] += v.w * Wg[(d + 3) * NE + e];
        }
    }
#pragma unroll
    for (int e = 0; e < NE; e++)
#pragma unroll
        for (int off = 16; off > 0; off >>= 1)
            acc[e] += __shfl_xor_sync(0xffffffffu, acc[e], off);

    if (lane == 0) {
        float l0 = -1e30f; int e0 = 0;
#pragma unroll
        for (int e = 0; e < NE; e++) if (acc[e] > l0) { l0 = acc[e]; e0 = e; }
        float l1 = -1e30f; int e1 = 0;
#pragma unroll
        for (int e = 0; e < NE; e++) if (e != e0 && acc[e] > l1) { l1 = acc[e]; e1 = e; }
        float w0 = 1.f / (1.f + __expf(l1 - l0));
        g_te[2 * t]     = e0;  g_te[2 * t + 1] = e1;
        g_tw[2 * t]     = w0;  g_tw[2 * t + 1] = 1.f - w0;
    }
}

// ---------------- parallel ordered capacity scan (hist/prefix/place) ---------
__global__ void __launch_bounds__(256) hist_kernel() {
    __shared__ int s_wtot[8][NE];
    int tid = threadIdx.x, wid = tid >> 5, lane = tid & 31;
    int i = blockIdx.x * 256 + tid;
    int e = g_te[i];
#pragma unroll
    for (int ee = 0; ee < NE; ee++) {
        unsigned m = __ballot_sync(0xffffffffu, e == ee);
        if (lane == 0) s_wtot[wid][ee] = __popc(m);
    }
    __syncthreads();
    if (tid < NE) {
        int tot = 0;
#pragma unroll
        for (int w = 0; w < 8; w++) tot += s_wtot[w][tid];
        g_blkcnt[blockIdx.x * NE + tid] = tot;
    }
}

__global__ void __launch_bounds__(32) prefix_kernel() {
    int e = threadIdx.x;
    if (e >= NE) return;
    int run = 0;
    for (int s = 0; s < NSEG; s++) {
        g_segoff[s * NE + e] = run;
        run += g_blkcnt[s * NE + e];
    }
    g_run[e] = run;
    g_cnt[e] = min(run, CAPACITY);
}

__global__ void __launch_bounds__(256) place_kernel() {
    __shared__ int s_wtot[8][NE];
    __shared__ int s_base[NE];
    int tid = threadIdx.x, wid = tid >> 5, lane = tid & 31;
    int i = blockIdx.x * 256 + tid;
    int e = g_te[i];
    int rank = 0;
#pragma unroll
    for (int ee = 0; ee < NE; ee++) {
        unsigned m = __ballot_sync(0xffffffffu, e == ee);
        if (e == ee) rank = __popc(m & ((1u << lane) - 1u));
        if (lane == 0) s_wtot[wid][ee] = __popc(m);
    }
    if (tid < NE) s_base[tid] = g_segoff[blockIdx.x * NE + tid];
    __syncthreads();
    int off = s_base[e];
    for (int w = 0; w < wid; w++) off += s_wtot[w][e];
    int pos = off + rank;
    if (pos < CAPACITY) {
        g_src[e * CAPACITY + pos] = i >> 1;
        g_cidx[i] = e * CAPACITY + pos;
        g_cw[i]   = g_tw[i];
    } else {
        g_cidx[i] = 0;
        g_cw[i]   = 0.f;
    }
}

__global__ void __launch_bounds__(256) pad_kernel() {
    int idx = blockIdx.x * 256 + threadIdx.x;
    if (idx >= NE * CAPACITY) return;
    int e = idx / CAPACITY, c = idx % CAPACITY;
    if (c >= g_cnt[e]) g_src[idx] = 0;
}

// ---------------- dispatch: gather x rows into chunked swizzled A ------------
__global__ void __launch_bounds__(256) dispatch_kernel(const float* __restrict__ x) {
    int slot = blockIdx.x;                 // 0 .. NE*CAPACITY-1
    int e  = slot / CAPACITY;
    int sl = slot % CAPACITY;
    int mt = sl >> 8, row = sl & 255;
    int tok = g_src[slot];
    int t = threadIdx.x;
    int k = t >> 3, seg = t & 7;           // chunk k (0..31), 16B segment (0..7)

    float4 v = *reinterpret_cast<const float4*>(x + (size_t)tok * DM + k * 32 + seg * 4);
    v.x = to_tf32(v.x); v.y = to_tf32(v.y); v.z = to_tf32(v.z); v.w = to_tf32(v.w);

    size_t cb = (((size_t)e * MT1 + mt) * NCH1 + k) * CHUNK_BYTES;
    uint32_t off = swz((uint32_t)(row * 128 + seg * 16));
    *reinterpret_cast<float4*>(reinterpret_cast<char*>(g_abuf) + cb + off) = v;
}

// ---------------- repack W: transpose + round + chunk + swizzle ---------------
__global__ void __launch_bounds__(256) repack_w_kernel(const float* __restrict__ W,
                                                       float* __restrict__ Wc,
                                                       int KD, int ND) {
    __shared__ float t[32][33];
    int e = blockIdx.z;
    int n0 = blockIdx.x * 32, k0 = blockIdx.y * 32;
    const float* src = W + (size_t)e * KD * ND;
    int tx = threadIdx.x & 31, ty = threadIdx.x >> 5;   // 32 x 8
#pragma unroll
    for (int r = 0; r < 32; r += 8)
        t[ty + r][tx] = src[(size_t)(k0 + ty + r) * ND + n0 + tx];
    __syncthreads();
    int nchunks = KD >> 5;
    int chunk = k0 >> 5;
#pragma unroll
    for (int r = 0; r < 32; r += 8) {
        int n = n0 + ty + r;
        int k = k0 + tx;
        float val = to_tf32(t[tx][ty + r]);
        size_t cb = (((size_t)e * (ND >> 8) + (n >> 8)) * nchunks + chunk) * CHUNK_BYTES;
        uint32_t off = swz((uint32_t)((n & 255) * 128 + (k & 31) * 4));
        *reinterpret_cast<float*>(reinterpret_cast<char*>(Wc) + cb + off) = val;
    }
}

// ---------------- grouped GEMM: bulk-TMA warp-specialized tcgen05 -------------
#define BMP 256
#define BN 256
#define STAGES 3
#define STAGE_BYTES (2*CHUNK_BYTES)        // A 32KB + B 32KB
#define SMEM_SZ (2048 + STAGES*STAGE_BYTES)

// idesc: c=F32(1<<4), a=TF32(2<<7), b=TF32(2<<10), N=256 (32<<17), M=128 (8<<24)
#define IDESC ((1u<<4) | (2u<<7) | (2u<<10) | ((BN/8)<<17) | ((128/16)<<24))

template <int WHICH>
__global__ void __launch_bounds__(256, 1) moe_gemm_tc(const float* __restrict__ Wsrc,
                                                      const float* __restrict__ Xsrc) {
    constexpr int Kd  = (WHICH == 1) ? DM : DFF;
    constexpr int Nd  = (WHICH == 1) ? DFF : DM;
    constexpr int NCH = Kd / 32;

    int e  = blockIdx.z;
    int mt = blockIdx.x;
    int nt = blockIdx.y;
    int m0 = mt * BMP;
    int n0 = nt * BN;
    if (m0 >= g_cnt[e]) return;

    extern __shared__ char smem[];
    int tid = threadIdx.x, wid = tid >> 5, lane = tid & 31;

#if HAS_TC
    (void)Wsrc; (void)Xsrc;
    uint32_t sb = smem_u32(smem);
    uint32_t tmp_addr = sb;                       // tcgen05.alloc result
    uint32_t mb_full  = sb + 16;                  // 3 x 8B
    uint32_t mb_empty = sb + 40;                  // 3 x 8B
    uint32_t mb_done  = sb + 64;
    uint32_t stage0 = (sb + 128 + 1023) & ~1023u;

    const char* abase;
    if (WHICH == 1) abase = reinterpret_cast<const char*>(g_abuf)
                          + (((size_t)e * MT1 + mt) * NCH1) * CHUNK_BYTES;
    else            abase = reinterpret_cast<const char*>(g_h)
                          + (((size_t)e * MT1 + mt) * NCH2) * CHUNK_BYTES;
    const char* bbase;
    if (WHICH == 1) bbase = reinterpret_cast<const char*>(g_w1t)
                          + (((size_t)e * NT1 + nt) * NCH1) * CHUNK_BYTES;
    else            bbase = reinterpret_cast<const char*>(g_w2t)
                          + (((size_t)e * NT2 + nt) * NCH2) * CHUNK_BYTES;

    if (tid == 0) {
        for (int j = 0; j < 3; j++) { mbar_init(mb_full + j * 8, 1); mbar_init(mb_empty + j * 8, 1); }
        mbar_init(mb_done, 1);
        FENCE_ASYNC_SHARED();
    }
    if (wid == 0) TC_ALLOC(tmp_addr, 512);
    __syncthreads();
    uint32_t tmem;
    asm volatile("ld.shared.b32 %0, [%1];" : "=r"(tmem) : "r"(tmp_addr));

    if (tid == 0) {
        // ---- producer: one bulk copy per operand per chunk ----
        for (int i = 0; i < NCH; i++) {
            int s = i % 3, ep = i / 3;
            if (ep >= 1) mbar_wait(mb_empty + s * 8, (ep - 1) & 1);
            uint32_t st = stage0 + s * STAGE_BYTES;
            mbar_expect_tx(mb_full + s * 8, STAGE_BYTES);
            bulk_g2s(st,               abase + (size_t)i * CHUNK_BYTES, CHUNK_BYTES, mb_full + s * 8);
            bulk_g2s(st + CHUNK_BYTES, bbase + (size_t)i * CHUNK_BYTES, CHUNK_BYTES, mb_full + s * 8);
        }
    } else if (tid == 32) {
        // ---- MMA issue ----
        for (int i = 0; i < NCH; i++) {
            int s = i % 3, ep = i / 3;
            mbar_wait(mb_full + s * 8, ep & 1);
            uint64_t ad0 = mkdesc(stage0 + s * STAGE_BYTES);
            uint64_t ad1 = ad0 + 1024;                       // +128 rows
            uint64_t bd  = mkdesc(stage0 + s * STAGE_BYTES + CHUNK_BYTES);
#pragma unroll
            for (int st = 0; st < 4; st++) {
                uint32_t en = (i > 0) || (st > 0);
                mma_tf32_ss(tmem,       ad0 + st * 2, bd + st * 2, IDESC, en);
                mma_tf32_ss(tmem + 256, ad1 + st * 2, bd + st * 2, IDESC, en);
            }
            TC_COMMIT(mb_empty + s * 8);
        }
        TC_COMMIT(mb_done);
    }

    // ---- all threads: wait for final MMA, then epilogue ----
    mbar_wait(mb_done, 0);
    TC_FENCE_AFTER();

    int part = wid & 3, tb = wid >> 2;
    int srow = tb * 128 + part * 32 + lane;             // row within 256-tile
    uint32_t dbase = tmem + tb * 256;
    if (WHICH == 1) {
        // write h in GEMM2's chunked layout
        char* hb = reinterpret_cast<char*>(g_h)
                 + (((size_t)e * MT1 + mt) * NCH2 + (n0 >> 5)) * CHUNK_BYTES;
#pragma unroll
        for (int b = 0; b < 8; b++) {
            uint32_t u[32];
            TC_LD_X32(u, dbase + b * 32);
            TC_WAIT_LD();
            char* cb = hb + (size_t)b * CHUNK_BYTES;
#pragma unroll
            for (int c = 0; c < 32; c += 4) {
                float4 v = make_float4(
                    to_tf32(gelu_tanh(__uint_as_float(u[c + 0]))),
                    to_tf32(gelu_tanh(__uint_as_float(u[c + 1]))),
                    to_tf32(gelu_tanh(__uint_as_float(u[c + 2]))),
                    to_tf32(gelu_tanh(__uint_as_float(u[c + 3]))));
                uint32_t off = swz((uint32_t)(srow * 128 + (c >> 2) * 16));
                *reinterpret_cast<float4*>(cb + off) = v;
            }
        }
    } else {
        float* outp = g_y + ((size_t)(e * CAPACITY + m0 + srow)) * Nd + n0;
#pragma unroll
        for (int b = 0; b < 8; b++) {
            uint32_t u[32];
            TC_LD_X32(u, dbase + b * 32);
            TC_WAIT_LD();
#pragma unroll
            for (int c = 0; c < 32; c += 4) {
                float4 v = make_float4(__uint_as_float(u[c + 0]), __uint_as_float(u[c + 1]),
                                       __uint_as_float(u[c + 2]), __uint_as_float(u[c + 3]));
                *reinterpret_cast<float4*>(outp + b * 32 + c) = v;
            }
        }
    }
    TC_FENCE_BEFORE();
    __syncthreads();
    if (wid == 0) {
        TC_RELINQ();
        TC_DEALLOC(tmem, 512);
    }
#else
    // ================= tf32 wmma fallback (row-major h; internally consistent) =====
    using namespace nvcuda;
    constexpr int BM = 128;
    constexpr int BK = 16;
    constexpr int NKS = Kd / BK;
    const float* We = Wsrc + (size_t)e * Kd * Nd;
    float* As = reinterpret_cast<float*>(smem);
    float* Bs = As + 2 * BM * (BK + 4);
    const float** s_arow = reinterpret_cast<const float**>(Bs + 2 * BK * (BN + 8));

    for (int h128 = 0; h128 < 2; h128++) {
        int m0h = m0 + h128 * BM;
        for (int r = tid; r < BM; r += 256) {
            if (WHICH == 1) s_arow[r] = Xsrc + (size_t)g_src[e * CAPACITY + m0h + r] * Kd;
            else            s_arow[r] = g_h + (size_t)(e * CAPACITY + m0h + r) * Kd;
        }
        __syncthreads();
        auto Aat = [&](int buf, int r, int c) -> float& { return As[(buf * BM + r) * (BK + 4) + c]; };
        auto Bat = [&](int buf, int r, int c) -> float& { return Bs[(buf * BK + r) * (BN + 8) + c]; };
        auto loadA = [&](int buf, int k0) {
#pragma unroll
            for (int it = 0; it < 2; it++) {
                int idx = tid * 2 + it;
                int r = idx >> 2, q = idx & 3;
                float4 v = *reinterpret_cast<const float4*>(s_arow[r] + k0 + q * 4);
                *reinterpret_cast<float4*>(&Aat(buf, r, q * 4)) = v;
            }
        };
        auto loadB = [&](int buf, int k0) {
#pragma unroll
            for (int it = 0; it < 4; it++) {
                int idx = tid + it * 256;
                int r = idx >> 6, c = idx & 63;
                float4 v = *reinterpret_cast<const float4*>(We + (size_t)(k0 + r) * Nd + n0 + c * 4);
                *reinterpret_cast<float4*>(&Bat(buf, r, c * 4)) = v;
            }
        };
        typedef wmma::fragment<wmma::matrix_a, 16, 16, 8, wmma::precision::tf32, wmma::row_major> FragA;
        typedef wmma::fragment<wmma::matrix_b, 16, 16, 8, wmma::precision::tf32, wmma::row_major> FragB;
        typedef wmma::fragment<wmma::accumulator, 16, 16, 8, float> FragC;
        FragC acc[4][4];
#pragma unroll
        for (int i = 0; i < 4; i++)
#pragma unroll
            for (int j = 0; j < 4; j++) wmma::fill_fragment(acc[i][j], 0.f);
        int wm = wid >> 2, wn = wid & 3;
        loadA(0, 0); loadB(0, 0);
        __syncthreads();
        for (int ks = 0; ks < NKS; ks++) {
            int cur = ks & 1;
            if (ks + 1 < NKS) { loadA(cur ^ 1, (ks + 1) * BK); loadB(cur ^ 1, (ks + 1) * BK); }
#pragma unroll
            for (int kk = 0; kk < 2; kk++) {
                FragA af[4]; FragB bf[4];
#pragma unroll
                for (int i = 0; i < 4; i++) {
                    wmma::load_matrix_sync(af[i], &Aat(cur, wm * 64 + i * 16, kk * 8), BK + 4);
#pragma unroll
                    for (int t = 0; t < af[i].num_elements; t++)
                        af[i].x[t] = wmma::__float_to_tf32(af[i].x[t]);
                }
#pragma unroll
                for (int j = 0; j < 4; j++) {
                    wmma::load_matrix_sync(bf[j], &Bat(cur, kk * 8, wn * 64 + j * 16), BN + 8);
#pragma unroll
                    for (int t = 0; t < bf[j].num_elements; t++)
                        bf[j].x[t] = wmma::__float_to_tf32(bf[j].x[t]);
                }
#pragma unroll
                for (int i = 0; i < 4; i++)
#pragma unroll
                    for (int j = 0; j < 4; j++)
                        wmma::mma_sync(acc[i][j], af[i], bf[j], acc[i][j]);
            }
            __syncthreads();
        }
        float* Cb = ((WHICH == 1) ? g_h : g_y) + (size_t)(e * CAPACITY + m0h) * Nd + n0;
#pragma unroll
        for (int i = 0; i < 4; i++)
#pragma unroll
            for (int j = 0; j < 4; j++) {
                if (WHICH == 1) {
#pragma unroll
                    for (int t = 0; t < acc[i][j].num_elements; t++)
                        acc[i][j].x[t] = to_tf32(gelu_tanh(acc[i][j].x[t]));
                }
                wmma::store_matrix_sync(Cb + (size_t)(wm * 64 + i * 16) * Nd + wn * 64 + j * 16,
                                        acc[i][j], Nd, wmma::mem_row_major);
            }
        __syncthreads();
    }
#endif
}

// ---------------- combine -----------------------------------------------------
__global__ void __launch_bounds__(256) combine_kernel(float* __restrict__ out) {
    int t   = blockIdx.x;
    int tid = threadIdx.x;
    int i0 = g_cidx[2 * t],     i1 = g_cidx[2 * t + 1];
    float w0 = g_cw[2 * t],     w1 = g_cw[2 * t + 1];
    const float4* y0 = reinterpret_cast<const float4*>(g_y + (size_t)i0 * DM);
    const float4* y1 = reinterpret_cast<const float4*>(g_y + (size_t)i1 * DM);
    float4 a = y0[tid], b = y1[tid];
    float4 r;
    r.x = w0 * a.x + w1 * b.x;
    r.y = w0 * a.y + w1 * b.y;
    r.z = w0 * a.z + w1 * b.z;
    r.w = w0 * a.w + w1 * b.w;
    reinterpret_cast<float4*>(out + (size_t)t * DM)[tid] = r;
}

// ---------------- launch ------------------------------------------------------
extern "C" void kernel_launch(void* const* d_in, const int* in_sizes, int n_in,
                              void* d_out, int out_size) {
    const float* x  = (const float*)d_in[0];   // [T, D]
    const float* Wg = (const float*)d_in[1];   // [D, E]
    const float* W1 = (const float*)d_in[2];   // [E, D, H]
    const float* W2 = (const float*)d_in[3];   // [E, H, D]
    float* out = (float*)d_out;                // [T, D]

    cudaFuncSetAttribute(moe_gemm_tc<1>, cudaFuncAttributeMaxDynamicSharedMemorySize, SMEM_SZ);
    cudaFuncSetAttribute(moe_gemm_tc<2>, cudaFuncAttributeMaxDynamicSharedMemorySize, SMEM_SZ);

    router_kernel<<<NT / 8, 256>>>(x, Wg);
    {
        float* w1t; cudaGetSymbolAddress((void**)&w1t, g_w1t);
        repack_w_kernel<<<dim3(DFF / 32, DM / 32, NE), 256>>>(W1, w1t, DM, DFF);
    }
    {
        float* w2t; cudaGetSymbolAddress((void**)&w2t, g_w2t);
        repack_w_kernel<<<dim3(DM / 32, DFF / 32, NE), 256>>>(W2, w2t, DFF, DM);
    }
    hist_kernel<<<NSEG, 256>>>();
    prefix_kernel<<<1, 32>>>();
    place_kernel<<<NSEG, 256>>>();
    pad_kernel<<<(NE * CAPACITY + 255) / 256, 256>>>();
    dispatch_kernel<<<NE * CAPACITY, 256>>>(x);
    moe_gemm_tc<1><<<dim3(MT1, NT1, NE), 256, SMEM_SZ>>>(W1, x);
    moe_gemm_tc<2><<<dim3(MT1, NT2, NE), 256, SMEM_SZ>>>(W2, x);
    combine_kernel<<<NT, 256>>>(out);
}